// round 1
// baseline (speedup 1.0000x reference)
#include <cuda_runtime.h>

// Problem constants
#define B_  8
#define T_  1024
#define D_  1024
#define H_  16
#define DH_ 64
#define BT  (B_*T_)        // 8192
#define D3  (3*D_)         // 3072

// GEMM tiling
#define BM 64
#define BN 64
#define BK 16
#define PAD 4

// Scratch (allocation-free: __device__ globals)
static __device__ float g_qkv[(long)BT * D3];            // [b*t][3*D]  96 MB
static __device__ float g_scoresT[(long)B_*H_*T_*T_];    // [b*h][k][q] 512 MB
static __device__ float g_attn_out[(long)BT * D_];       // [b*t][D]    32 MB

// ---------------------------------------------------------------------------
// NT GEMM body: C[m,n] = alpha * sum_k A[m*lda + k] * B[n*ldb + k]
// A, B, C already offset to this block's tile origin. 256 threads.
// ---------------------------------------------------------------------------
__device__ __forceinline__ void gemm_nt_body(
    const float* __restrict__ A, const float* __restrict__ B, float* __restrict__ C,
    int K, int lda, int ldb, int ldc, float alpha)
{
    __shared__ float As[BK][BM + PAD];
    __shared__ float Bs[BK][BN + PAD];

    const int tid = threadIdx.x;
    const int tx = tid & 15;          // output column group
    const int ty = tid >> 4;          // output row group
    const int lr = tid >> 2;          // 0..63 tile row for loading
    const int lc = (tid & 3) << 2;    // 0,4,8,12 k-subcolumn

    const float* Ag = A + (long)lr * lda + lc;
    const float* Bg = B + (long)lr * ldb + lc;

    float acc[4][4];
#pragma unroll
    for (int i = 0; i < 4; ++i)
#pragma unroll
        for (int j = 0; j < 4; ++j) acc[i][j] = 0.0f;

    for (int k0 = 0; k0 < K; k0 += BK) {
        float4 av = *(const float4*)(Ag + k0);
        float4 bv = *(const float4*)(Bg + k0);
        As[lc + 0][lr] = av.x; As[lc + 1][lr] = av.y;
        As[lc + 2][lr] = av.z; As[lc + 3][lr] = av.w;
        Bs[lc + 0][lr] = bv.x; Bs[lc + 1][lr] = bv.y;
        Bs[lc + 2][lr] = bv.z; Bs[lc + 3][lr] = bv.w;
        __syncthreads();

#pragma unroll
        for (int kk = 0; kk < BK; ++kk) {
            float4 ra = *(const float4*)(&As[kk][ty << 2]);
            float4 rb = *(const float4*)(&Bs[kk][tx << 2]);
            float a[4] = {ra.x, ra.y, ra.z, ra.w};
            float b[4] = {rb.x, rb.y, rb.z, rb.w};
#pragma unroll
            for (int i = 0; i < 4; ++i)
#pragma unroll
                for (int j = 0; j < 4; ++j) acc[i][j] += a[i] * b[j];
        }
        __syncthreads();
    }

#pragma unroll
    for (int i = 0; i < 4; ++i) {
        float4 o;
        o.x = acc[i][0] * alpha; o.y = acc[i][1] * alpha;
        o.z = acc[i][2] * alpha; o.w = acc[i][3] * alpha;
        *(float4*)(C + (long)((ty << 2) + i) * ldc + (tx << 2)) = o;
    }
}

// ---------------------------------------------------------------------------
// TN GEMM body: C[m,n] = alpha * sum_k A[k*lda + m] * B[k*ldb + n]
// ---------------------------------------------------------------------------
__device__ __forceinline__ void gemm_tn_body(
    const float* __restrict__ A, const float* __restrict__ B, float* __restrict__ C,
    int K, int lda, int ldb, int ldc, float alpha)
{
    __shared__ float As[BK][BM + PAD];
    __shared__ float Bs[BK][BN + PAD];

    const int tid = threadIdx.x;
    const int tx = tid & 15;
    const int ty = tid >> 4;
    const int r  = tid >> 4;          // 0..15 k-row for loading
    const int c  = (tid & 15) << 2;   // 0..60 column

    float acc[4][4];
#pragma unroll
    for (int i = 0; i < 4; ++i)
#pragma unroll
        for (int j = 0; j < 4; ++j) acc[i][j] = 0.0f;

    for (int k0 = 0; k0 < K; k0 += BK) {
        float4 av = *(const float4*)(A + (long)(k0 + r) * lda + c);
        float4 bv = *(const float4*)(B + (long)(k0 + r) * ldb + c);
        *(float4*)(&As[r][c]) = av;
        *(float4*)(&Bs[r][c]) = bv;
        __syncthreads();

#pragma unroll
        for (int kk = 0; kk < BK; ++kk) {
            float4 ra = *(const float4*)(&As[kk][ty << 2]);
            float4 rb = *(const float4*)(&Bs[kk][tx << 2]);
            float a[4] = {ra.x, ra.y, ra.z, ra.w};
            float b[4] = {rb.x, rb.y, rb.z, rb.w};
#pragma unroll
            for (int i = 0; i < 4; ++i)
#pragma unroll
                for (int j = 0; j < 4; ++j) acc[i][j] += a[i] * b[j];
        }
        __syncthreads();
    }

#pragma unroll
    for (int i = 0; i < 4; ++i) {
        float4 o;
        o.x = acc[i][0] * alpha; o.y = acc[i][1] * alpha;
        o.z = acc[i][2] * alpha; o.w = acc[i][3] * alpha;
        *(float4*)(C + (long)((ty << 2) + i) * ldc + (tx << 2)) = o;
    }
}

// ---------------------------------------------------------------------------
// Stage 1: qkv = x @ W_qkv^T     [8192,1024] x [3072,1024]^T -> [8192,3072]
// ---------------------------------------------------------------------------
__global__ void k_qkv(const float* __restrict__ x, const float* __restrict__ w)
{
    const float* A = x + (long)blockIdx.y * BM * D_;
    const float* Bp = w + (long)blockIdx.x * BN * D_;
    float* C = g_qkv + (long)blockIdx.y * BM * D3 + blockIdx.x * BN;
    gemm_nt_body(A, Bp, C, D_, D_, D_, D3, 1.0f);
}

// ---------------------------------------------------------------------------
// Stage 2: S'[bh][k][q] = scale * sum_d K[k,d] * Q[q,d]   (S transposed!)
// grid: (T/BN, T/BM, B*H)
// ---------------------------------------------------------------------------
__global__ void k_scores()
{
    const int z = blockIdx.z;
    const int b = z >> 4;
    const int h = z & 15;
    const float* base = g_qkv + (long)b * T_ * D3 + h * DH_;
    const float* A  = base + D_     + (long)blockIdx.y * BM * D3;  // K rows
    const float* Bp = base          + (long)blockIdx.x * BN * D3;  // Q rows
    float* C = g_scoresT + (long)z * T_ * T_ + (long)blockIdx.y * BM * T_ + blockIdx.x * BN;
    gemm_nt_body(A, Bp, C, DH_, D3, D3, T_, 0.125f);   // DH^-0.5 = 1/8
}

// ---------------------------------------------------------------------------
// Stage 3: row softmax over the q axis (rows of S' are contiguous in q).
// One block per row of 1024. 256 threads, float4 each.
// ---------------------------------------------------------------------------
__global__ void k_softmax()
{
    const long row = blockIdx.x;
    float* p = g_scoresT + row * T_;
    const int t = threadIdx.x;

    float4 x = ((float4*)p)[t];
    float m = fmaxf(fmaxf(x.x, x.y), fmaxf(x.z, x.w));

    __shared__ float red[8];
#pragma unroll
    for (int o = 16; o > 0; o >>= 1) m = fmaxf(m, __shfl_xor_sync(0xffffffffu, m, o));
    if ((t & 31) == 0) red[t >> 5] = m;
    __syncthreads();
    float M = red[0];
#pragma unroll
    for (int i = 1; i < 8; ++i) M = fmaxf(M, red[i]);
    __syncthreads();

    float4 e;
    e.x = __expf(x.x - M); e.y = __expf(x.y - M);
    e.z = __expf(x.z - M); e.w = __expf(x.w - M);
    float s = (e.x + e.y) + (e.z + e.w);
#pragma unroll
    for (int o = 16; o > 0; o >>= 1) s += __shfl_xor_sync(0xffffffffu, s, o);
    if ((t & 31) == 0) red[t >> 5] = s;
    __syncthreads();
    float S = red[0];
#pragma unroll
    for (int i = 1; i < 8; ++i) S += red[i];

    const float r = 1.0f / S;
    e.x *= r; e.y *= r; e.z *= r; e.w *= r;
    ((float4*)p)[t] = e;
}

// ---------------------------------------------------------------------------
// Stage 4: out[b,q,h,d] = sum_k P'[k,q] * V[k,d]   (TN GEMM per (b,h))
// grid: (1, T/BM, B*H); N = DH = 64 = one tile.
// ---------------------------------------------------------------------------
__global__ void k_attnv()
{
    const int z = blockIdx.z;
    const int b = z >> 4;
    const int h = z & 15;
    const float* A  = g_scoresT + (long)z * T_ * T_ + blockIdx.y * BM;        // P'[k][q]
    const float* Bp = g_qkv + (long)b * T_ * D3 + 2 * D_ + h * DH_;           // V[k][d]
    float* C = g_attn_out + ((long)b * T_ + blockIdx.y * BM) * D_ + h * DH_;
    gemm_tn_body(A, Bp, C, T_, T_, D3, D_, 1.0f);
}

// ---------------------------------------------------------------------------
// Stage 5: y = attn_out @ W_proj^T   [8192,1024] x [1024,1024]^T
// ---------------------------------------------------------------------------
__global__ void k_proj(const float* __restrict__ wproj, float* __restrict__ out)
{
    const float* A = g_attn_out + (long)blockIdx.y * BM * D_;
    const float* Bp = wproj + (long)blockIdx.x * BN * D_;
    float* C = out + (long)blockIdx.y * BM * D_ + blockIdx.x * BN;
    gemm_nt_body(A, Bp, C, D_, D_, D_, D_, 1.0f);
}

// ---------------------------------------------------------------------------
extern "C" void kernel_launch(void* const* d_in, const int* in_sizes, int n_in,
                              void* d_out, int out_size)
{
    const float* x      = (const float*)d_in[0];   // [8,1024,1024]
    const float* w_qkv  = (const float*)d_in[1];   // [3072,1024]
    const float* w_proj = (const float*)d_in[2];   // [1024,1024]
    float* out = (float*)d_out;                    // [8,1024,1024]

    // 1) QKV projection
    k_qkv<<<dim3(D3 / BN, BT / BM), 256>>>(x, w_qkv);

    // 2) S' = scale * K Q^T  per (b,h)
    k_scores<<<dim3(T_ / BN, T_ / BM, B_ * H_), 256>>>();

    // 3) softmax over q (rows of S')
    k_softmax<<<(long)B_ * H_ * T_, 256>>>();

    // 4) attn @ V
    k_attnv<<<dim3(1, T_ / BM, B_ * H_), 256>>>();

    // 5) output projection
    k_proj<<<dim3(D_ / BN, BT / BM), 256>>>(w_proj, out);
}

// round 2
// speedup vs baseline: 1.0010x; 1.0010x over previous
#include <cuda_runtime.h>

// Problem constants
#define B_  8
#define T_  1024
#define D_  1024
#define H_  16
#define DH_ 64
#define BT  (B_*T_)        // 8192
#define D3  (3*D_)         // 3072

// GEMM tiling
#define BM 64
#define BN 64
#define BK 16
#define PAD 4

// Scratch (allocation-free: __device__ globals)
static __device__ float g_qkv[(long)BT * D3];            // [b*t][3*D]  96 MB
static __device__ float g_scoresT[(long)B_*H_*T_*T_];    // [b*h][k][q] 512 MB
static __device__ float g_attn_out[(long)BT * D_];       // [b*t][D]    32 MB

// ---------------------------------------------------------------------------
// NT GEMM body: C[m,n] = alpha * sum_k A[m*lda + k] * B[n*ldb + k]
// A, B, C already offset to this block's tile origin. 256 threads.
// ---------------------------------------------------------------------------
__device__ __forceinline__ void gemm_nt_body(
    const float* __restrict__ A, const float* __restrict__ B, float* __restrict__ C,
    int K, int lda, int ldb, int ldc, float alpha)
{
    __shared__ float As[BK][BM + PAD];
    __shared__ float Bs[BK][BN + PAD];

    const int tid = threadIdx.x;
    const int tx = tid & 15;          // output column group
    const int ty = tid >> 4;          // output row group
    const int lr = tid >> 2;          // 0..63 tile row for loading
    const int lc = (tid & 3) << 2;    // 0,4,8,12 k-subcolumn

    const float* Ag = A + (long)lr * lda + lc;
    const float* Bg = B + (long)lr * ldb + lc;

    float acc[4][4];
#pragma unroll
    for (int i = 0; i < 4; ++i)
#pragma unroll
        for (int j = 0; j < 4; ++j) acc[i][j] = 0.0f;

    for (int k0 = 0; k0 < K; k0 += BK) {
        float4 av = *(const float4*)(Ag + k0);
        float4 bv = *(const float4*)(Bg + k0);
        As[lc + 0][lr] = av.x; As[lc + 1][lr] = av.y;
        As[lc + 2][lr] = av.z; As[lc + 3][lr] = av.w;
        Bs[lc + 0][lr] = bv.x; Bs[lc + 1][lr] = bv.y;
        Bs[lc + 2][lr] = bv.z; Bs[lc + 3][lr] = bv.w;
        __syncthreads();

#pragma unroll
        for (int kk = 0; kk < BK; ++kk) {
            float4 ra = *(const float4*)(&As[kk][ty << 2]);
            float4 rb = *(const float4*)(&Bs[kk][tx << 2]);
            float a[4] = {ra.x, ra.y, ra.z, ra.w};
            float b[4] = {rb.x, rb.y, rb.z, rb.w};
#pragma unroll
            for (int i = 0; i < 4; ++i)
#pragma unroll
                for (int j = 0; j < 4; ++j) acc[i][j] += a[i] * b[j];
        }
        __syncthreads();
    }

#pragma unroll
    for (int i = 0; i < 4; ++i) {
        float4 o;
        o.x = acc[i][0] * alpha; o.y = acc[i][1] * alpha;
        o.z = acc[i][2] * alpha; o.w = acc[i][3] * alpha;
        *(float4*)(C + (long)((ty << 2) + i) * ldc + (tx << 2)) = o;
    }
}

// ---------------------------------------------------------------------------
// TN GEMM body: C[m,n] = alpha * sum_k A[k*lda + m] * B[k*ldb + n]
// ---------------------------------------------------------------------------
__device__ __forceinline__ void gemm_tn_body(
    const float* __restrict__ A, const float* __restrict__ B, float* __restrict__ C,
    int K, int lda, int ldb, int ldc, float alpha)
{
    __shared__ float As[BK][BM + PAD];
    __shared__ float Bs[BK][BN + PAD];

    const int tid = threadIdx.x;
    const int tx = tid & 15;
    const int ty = tid >> 4;
    const int r  = tid >> 4;          // 0..15 k-row for loading
    const int c  = (tid & 15) << 2;   // 0..60 column

    float acc[4][4];
#pragma unroll
    for (int i = 0; i < 4; ++i)
#pragma unroll
        for (int j = 0; j < 4; ++j) acc[i][j] = 0.0f;

    for (int k0 = 0; k0 < K; k0 += BK) {
        float4 av = *(const float4*)(A + (long)(k0 + r) * lda + c);
        float4 bv = *(const float4*)(B + (long)(k0 + r) * ldb + c);
        *(float4*)(&As[r][c]) = av;
        *(float4*)(&Bs[r][c]) = bv;
        __syncthreads();

#pragma unroll
        for (int kk = 0; kk < BK; ++kk) {
            float4 ra = *(const float4*)(&As[kk][ty << 2]);
            float4 rb = *(const float4*)(&Bs[kk][tx << 2]);
            float a[4] = {ra.x, ra.y, ra.z, ra.w};
            float b[4] = {rb.x, rb.y, rb.z, rb.w};
#pragma unroll
            for (int i = 0; i < 4; ++i)
#pragma unroll
                for (int j = 0; j < 4; ++j) acc[i][j] += a[i] * b[j];
        }
        __syncthreads();
    }

#pragma unroll
    for (int i = 0; i < 4; ++i) {
        float4 o;
        o.x = acc[i][0] * alpha; o.y = acc[i][1] * alpha;
        o.z = acc[i][2] * alpha; o.w = acc[i][3] * alpha;
        *(float4*)(C + (long)((ty << 2) + i) * ldc + (tx << 2)) = o;
    }
}

// ---------------------------------------------------------------------------
// Stage 1: qkv = x @ W_qkv^T     [8192,1024] x [3072,1024]^T -> [8192,3072]
// ---------------------------------------------------------------------------
__global__ void k_qkv(const float* __restrict__ x, const float* __restrict__ w)
{
    const float* A = x + (long)blockIdx.y * BM * D_;
    const float* Bp = w + (long)blockIdx.x * BN * D_;
    float* C = g_qkv + (long)blockIdx.y * BM * D3 + blockIdx.x * BN;
    gemm_nt_body(A, Bp, C, D_, D_, D_, D3, 1.0f);
}

// ---------------------------------------------------------------------------
// Stage 2: S'[bh][k][q] = scale * sum_d K[k,d] * Q[q,d]   (S transposed!)
// grid: (T/BN, T/BM, B*H)
// ---------------------------------------------------------------------------
__global__ void k_scores()
{
    const int z = blockIdx.z;
    const int b = z >> 4;
    const int h = z & 15;
    const float* base = g_qkv + (long)b * T_ * D3 + h * DH_;
    const float* A  = base + D_     + (long)blockIdx.y * BM * D3;  // K rows
    const float* Bp = base          + (long)blockIdx.x * BN * D3;  // Q rows
    float* C = g_scoresT + (long)z * T_ * T_ + (long)blockIdx.y * BM * T_ + blockIdx.x * BN;
    gemm_nt_body(A, Bp, C, DH_, D3, D3, T_, 0.125f);   // DH^-0.5 = 1/8
}

// ---------------------------------------------------------------------------
// Stage 3: row softmax over the q axis (rows of S' are contiguous in q).
// One block per row of 1024. 256 threads, float4 each.
// ---------------------------------------------------------------------------
__global__ void k_softmax()
{
    const long row = blockIdx.x;
    float* p = g_scoresT + row * T_;
    const int t = threadIdx.x;

    float4 x = ((float4*)p)[t];
    float m = fmaxf(fmaxf(x.x, x.y), fmaxf(x.z, x.w));

    __shared__ float red[8];
#pragma unroll
    for (int o = 16; o > 0; o >>= 1) m = fmaxf(m, __shfl_xor_sync(0xffffffffu, m, o));
    if ((t & 31) == 0) red[t >> 5] = m;
    __syncthreads();
    float M = red[0];
#pragma unroll
    for (int i = 1; i < 8; ++i) M = fmaxf(M, red[i]);
    __syncthreads();

    float4 e;
    e.x = __expf(x.x - M); e.y = __expf(x.y - M);
    e.z = __expf(x.z - M); e.w = __expf(x.w - M);
    float s = (e.x + e.y) + (e.z + e.w);
#pragma unroll
    for (int o = 16; o > 0; o >>= 1) s += __shfl_xor_sync(0xffffffffu, s, o);
    if ((t & 31) == 0) red[t >> 5] = s;
    __syncthreads();
    float S = red[0];
#pragma unroll
    for (int i = 1; i < 8; ++i) S += red[i];

    const float r = 1.0f / S;
    e.x *= r; e.y *= r; e.z *= r; e.w *= r;
    ((float4*)p)[t] = e;
}

// ---------------------------------------------------------------------------
// Stage 4: out[b,q,h,d] = sum_k P'[k,q] * V[k,d]   (TN GEMM per (b,h))
// grid: (1, T/BM, B*H); N = DH = 64 = one tile.
// ---------------------------------------------------------------------------
__global__ void k_attnv()
{
    const int z = blockIdx.z;
    const int b = z >> 4;
    const int h = z & 15;
    const float* A  = g_scoresT + (long)z * T_ * T_ + blockIdx.y * BM;        // P'[k][q]
    const float* Bp = g_qkv + (long)b * T_ * D3 + 2 * D_ + h * DH_;           // V[k][d]
    float* C = g_attn_out + ((long)b * T_ + blockIdx.y * BM) * D_ + h * DH_;
    gemm_tn_body(A, Bp, C, T_, T_, D3, D_, 1.0f);
}

// ---------------------------------------------------------------------------
// Stage 5: y = attn_out @ W_proj^T   [8192,1024] x [1024,1024]^T
// ---------------------------------------------------------------------------
__global__ void k_proj(const float* __restrict__ wproj, float* __restrict__ out)
{
    const float* A = g_attn_out + (long)blockIdx.y * BM * D_;
    const float* Bp = wproj + (long)blockIdx.x * BN * D_;
    float* C = out + (long)blockIdx.y * BM * D_ + blockIdx.x * BN;
    gemm_nt_body(A, Bp, C, D_, D_, D_, D_, 1.0f);
}

// ---------------------------------------------------------------------------
extern "C" void kernel_launch(void* const* d_in, const int* in_sizes, int n_in,
                              void* d_out, int out_size)
{
    const float* x      = (const float*)d_in[0];   // [8,1024,1024]
    const float* w_qkv  = (const float*)d_in[1];   // [3072,1024]
    const float* w_proj = (const float*)d_in[2];   // [1024,1024]
    float* out = (float*)d_out;                    // [8,1024,1024]

    // 1) QKV projection
    k_qkv<<<dim3(D3 / BN, BT / BM), 256>>>(x, w_qkv);

    // 2) S' = scale * K Q^T  per (b,h)
    k_scores<<<dim3(T_ / BN, T_ / BM, B_ * H_), 256>>>();

    // 3) softmax over q (rows of S')
    k_softmax<<<(long)B_ * H_ * T_, 256>>>();

    // 4) attn @ V
    k_attnv<<<dim3(1, T_ / BM, B_ * H_), 256>>>();

    // 5) output projection
    k_proj<<<dim3(D_ / BN, BT / BM), 256>>>(w_proj, out);
}

// round 4
// speedup vs baseline: 3.3001x; 3.2968x over previous
#include <cuda_runtime.h>
#include <cuda_fp16.h>
#include <cstdint>

// Problem constants
#define B_  8
#define T_  1024
#define D_  1024
#define H_  16
#define DH_ 64
#define BT  (B_*T_)        // 8192
#define D3  (3*D_)         // 3072

// GEMM tiling
#define BM 128
#define BN 64
#define BK 32
#define KS 40              // smem row stride in halves (32 + 8 pad)

typedef unsigned int u32;

// Scratch (__device__ globals, allocation-free)
static __device__ __half g_qkv[(long)BT * D3];             // [t][3D] fp16, 48MB
static __device__ float  g_scoresT[(long)B_*H_*T_*T_];     // [bh][k][q] fp32, 512MB
static __device__ __half g_P[(long)B_*H_*T_*T_];           // [bh][k][q] fp16, 256MB
static __device__ __half g_Pt[(long)B_*H_*T_*T_];          // [bh][q][k] fp16, 256MB
static __device__ __half g_Vt[(long)B_*H_*DH_*T_];         // [bh][d][k] fp16, 16MB
static __device__ __half g_ao[(long)BT * D_];              // [t][D]   fp16, 16MB

// ---------------------------------------------------------------------------
// PTX helpers
// ---------------------------------------------------------------------------
__device__ __forceinline__ u32 smem_u32(const void* p) {
    return (u32)__cvta_generic_to_shared(p);
}
__device__ __forceinline__ void ldsm_x4(u32& r0, u32& r1, u32& r2, u32& r3, u32 a) {
    asm volatile("ldmatrix.sync.aligned.m8n8.x4.shared.b16 {%0,%1,%2,%3},[%4];"
                 : "=r"(r0), "=r"(r1), "=r"(r2), "=r"(r3) : "r"(a));
}
__device__ __forceinline__ void ldsm_x2(u32& r0, u32& r1, u32 a) {
    asm volatile("ldmatrix.sync.aligned.m8n8.x2.shared.b16 {%0,%1},[%2];"
                 : "=r"(r0), "=r"(r1) : "r"(a));
}
__device__ __forceinline__ void mma16816(float c[4],
                                         u32 a0, u32 a1, u32 a2, u32 a3,
                                         u32 b0, u32 b1) {
    asm volatile("mma.sync.aligned.m16n8k16.row.col.f32.f16.f16.f32 "
                 "{%0,%1,%2,%3},{%4,%5,%6,%7},{%8,%9},{%0,%1,%2,%3};"
                 : "+f"(c[0]), "+f"(c[1]), "+f"(c[2]), "+f"(c[3])
                 : "r"(a0), "r"(a1), "r"(a2), "r"(a3), "r"(b0), "r"(b1));
}

// ---------------------------------------------------------------------------
// Tile loaders: gmem -> smem[row][k] (K-contiguous, fp16, stride KS)
// ---------------------------------------------------------------------------
__device__ __forceinline__ void load_tile_f32(const float* __restrict__ A, long lda,
                                              __half* As, int rows, int k0) {
    const int t = threadIdx.x;
    const int r_ = t >> 3, c_ = (t & 7) * 4;
    for (int r0 = 0; r0 < rows; r0 += 32) {
        int r = r0 + r_;
        float4 v = *(const float4*)(A + (long)r * lda + k0 + c_);
        __half2* dst = (__half2*)(&As[r * KS + c_]);
        dst[0] = __floats2half2_rn(v.x, v.y);
        dst[1] = __floats2half2_rn(v.z, v.w);
    }
}
__device__ __forceinline__ void load_tile_f16(const __half* __restrict__ A, long lda,
                                              __half* As, int rows, int k0) {
    const int t = threadIdx.x;
    const int r_ = t >> 2, c_ = (t & 3) * 8;
    for (int r0 = 0; r0 < rows; r0 += 64) {
        int r = r0 + r_;
        *(uint4*)(&As[r * KS + c_]) = *(const uint4*)(A + (long)r * lda + k0 + c_);
    }
}

// ---------------------------------------------------------------------------
// NT GEMM body: C[m,n] = alpha * sum_k A[m][k] * B[n][k]
// A: BM x K, B: BN x K, both K-contiguous with leading dims lda/ldb.
// 256 threads = 8 warps (4 x 2). Warp tile 32x32.
// ---------------------------------------------------------------------------
template<bool AF32, bool BF32, bool CF32>
__device__ __forceinline__ void gemm_nt(const void* Ap, const void* Bp, void* Cp,
                                        int K, long lda, long ldb, long ldc, float alpha)
{
    __shared__ __half As[BM * KS];
    __shared__ __half Bs[BN * KS];

    const int t = threadIdx.x;
    const int warp = t >> 5, lane = t & 31;
    const int wm = warp >> 1, wn = warp & 1;

    float acc[2][4][4];
#pragma unroll
    for (int i = 0; i < 2; ++i)
#pragma unroll
        for (int j = 0; j < 4; ++j)
#pragma unroll
            for (int k = 0; k < 4; ++k) acc[i][j][k] = 0.0f;

    const u32 a_base = smem_u32(&As[(wm * 32 + (lane & 15)) * KS + (lane >> 4) * 8]);
    const u32 b_base = smem_u32(&Bs[(wn * 32 + (lane & 7)) * KS + ((lane >> 3) & 1) * 8]);

    for (int k0 = 0; k0 < K; k0 += BK) {
        if (AF32) load_tile_f32((const float*)Ap, lda, As, BM, k0);
        else      load_tile_f16((const __half*)Ap, lda, As, BM, k0);
        if (BF32) load_tile_f32((const float*)Bp, ldb, Bs, BN, k0);
        else      load_tile_f16((const __half*)Bp, ldb, Bs, BN, k0);
        __syncthreads();

#pragma unroll
        for (int ks = 0; ks < 2; ++ks) {
            u32 a[2][4], b[4][2];
#pragma unroll
            for (int mi = 0; mi < 2; ++mi)
                ldsm_x4(a[mi][0], a[mi][1], a[mi][2], a[mi][3],
                        a_base + (u32)((mi * 16 * KS + ks * 16) * 2));
#pragma unroll
            for (int ni = 0; ni < 4; ++ni)
                ldsm_x2(b[ni][0], b[ni][1],
                        b_base + (u32)((ni * 8 * KS + ks * 16) * 2));
#pragma unroll
            for (int mi = 0; mi < 2; ++mi)
#pragma unroll
                for (int ni = 0; ni < 4; ++ni)
                    mma16816(acc[mi][ni], a[mi][0], a[mi][1], a[mi][2], a[mi][3],
                             b[ni][0], b[ni][1]);
        }
        __syncthreads();
    }

    // Epilogue
    const int g = lane >> 2, tq = lane & 3;
#pragma unroll
    for (int mi = 0; mi < 2; ++mi) {
#pragma unroll
        for (int ni = 0; ni < 4; ++ni) {
            int row = wm * 32 + mi * 16 + g;
            int col = wn * 32 + ni * 8 + tq * 2;
            float v0 = acc[mi][ni][0] * alpha, v1 = acc[mi][ni][1] * alpha;
            float v2 = acc[mi][ni][2] * alpha, v3 = acc[mi][ni][3] * alpha;
            if (CF32) {
                float* C = (float*)Cp;
                *(float2*)(C + (long)row * ldc + col)       = make_float2(v0, v1);
                *(float2*)(C + (long)(row + 8) * ldc + col) = make_float2(v2, v3);
            } else {
                __half* C = (__half*)Cp;
                *(__half2*)(C + (long)row * ldc + col)       = __floats2half2_rn(v0, v1);
                *(__half2*)(C + (long)(row + 8) * ldc + col) = __floats2half2_rn(v2, v3);
            }
        }
    }
}

// ---------------------------------------------------------------------------
// 64x64 fp16 tile transpose: dst[c][r] = src[r][c]
// ---------------------------------------------------------------------------
__device__ __forceinline__ void trans64(const __half* __restrict__ src, long lds,
                                        __half* __restrict__ dst, long ldd)
{
    __shared__ __half tile[64 * 66];
    const int t = threadIdx.x;
    const int r_ = t >> 3, c_ = (t & 7) * 8;
#pragma unroll
    for (int p = 0; p < 2; ++p) {
        int r = r_ + p * 32;
        uint4 v = *(const uint4*)(src + (long)r * lds + c_);
        const __half* hv = (const __half*)&v;
#pragma unroll
        for (int j = 0; j < 8; ++j) tile[r * 66 + c_ + j] = hv[j];
    }
    __syncthreads();
#pragma unroll
    for (int p = 0; p < 2; ++p) {
        int r = r_ + p * 32;          // output row = source col
        uint4 v;
        __half* hv = (__half*)&v;
#pragma unroll
        for (int j = 0; j < 8; ++j) hv[j] = tile[(c_ + j) * 66 + r];
        *(uint4*)(dst + (long)r * ldd + c_) = v;
    }
}

// ---------------------------------------------------------------------------
// Stage kernels
// ---------------------------------------------------------------------------

// 1) qkv(fp16) = x(fp32) @ W_qkv(fp32)^T : [8192,3072]
__global__ void k_qkv(const float* __restrict__ x, const float* __restrict__ w)
{
    const float* A = x + (long)blockIdx.y * BM * D_;
    const float* Bp = w + (long)blockIdx.x * BN * D_;
    __half* C = g_qkv + (long)blockIdx.y * BM * D3 + blockIdx.x * BN;
    gemm_nt<true, true, false>(A, Bp, C, D_, D_, D_, D3, 1.0f);
}

// 2) S'[bh][k][q] = scale * K·Q^T (fp32 out)
__global__ void k_scores()
{
    const int z = blockIdx.z;
    const int b = z >> 4, h = z & 15;
    const __half* base = g_qkv + (long)b * T_ * D3 + h * DH_;
    const __half* A  = base + D_ + (long)blockIdx.y * BM * D3;   // K rows
    const __half* Bp = base      + (long)blockIdx.x * BN * D3;   // Q rows
    float* C = g_scoresT + (long)z * T_ * T_ + (long)blockIdx.y * BM * T_ + blockIdx.x * BN;
    gemm_nt<false, false, true>(A, Bp, C, DH_, D3, D3, T_, 0.125f);
}

// 3) softmax over q (rows of S'), write fp16 P
__global__ void k_softmax()
{
    const long row = blockIdx.x;
    const float* p = g_scoresT + row * T_;
    __half* po = g_P + row * T_;
    const int t = threadIdx.x;

    float4 x = ((const float4*)p)[t];
    float m = fmaxf(fmaxf(x.x, x.y), fmaxf(x.z, x.w));

    __shared__ float red[8];
#pragma unroll
    for (int o = 16; o > 0; o >>= 1) m = fmaxf(m, __shfl_xor_sync(0xffffffffu, m, o));
    if ((t & 31) == 0) red[t >> 5] = m;
    __syncthreads();
    float M = red[0];
#pragma unroll
    for (int i = 1; i < 8; ++i) M = fmaxf(M, red[i]);
    __syncthreads();

    float4 e;
    e.x = __expf(x.x - M); e.y = __expf(x.y - M);
    e.z = __expf(x.z - M); e.w = __expf(x.w - M);
    float s = (e.x + e.y) + (e.z + e.w);
#pragma unroll
    for (int o = 16; o > 0; o >>= 1) s += __shfl_xor_sync(0xffffffffu, s, o);
    if ((t & 31) == 0) red[t >> 5] = s;
    __syncthreads();
    float S = red[0];
#pragma unroll
    for (int i = 1; i < 8; ++i) S += red[i];

    const float r = 1.0f / S;
    __half2* o2 = (__half2*)(po + t * 4);
    o2[0] = __floats2half2_rn(e.x * r, e.y * r);
    o2[1] = __floats2half2_rn(e.z * r, e.w * r);
}

// 4a) P^T: g_Pt[bh][q][k] = g_P[bh][k][q]
__global__ void k_transP()
{
    const long z = blockIdx.z;
    const __half* src = g_P  + z * T_ * T_ + (long)blockIdx.y * 64 * T_ + blockIdx.x * 64;
    __half*       dst = g_Pt + z * T_ * T_ + (long)blockIdx.x * 64 * T_ + blockIdx.y * 64;
    trans64(src, T_, dst, T_);
}

// 4b) V^T: g_Vt[bh][d][k] = qkv V part
__global__ void k_transV()
{
    const int z = blockIdx.y;       // bh
    const int b = z >> 4, h = z & 15;
    const __half* src = g_qkv + ((long)b * T_ + blockIdx.x * 64) * D3 + 2 * D_ + h * DH_;
    __half*       dst = g_Vt + (long)z * DH_ * T_ + blockIdx.x * 64;
    trans64(src, D3, dst, T_);
}

// 5) out16[q, h*64+d] = sum_k Pt[q][k] * Vt[d][k]
__global__ void k_attnv()
{
    const int z = blockIdx.z;
    const int b = z >> 4, h = z & 15;
    const __half* A  = g_Pt + (long)z * T_ * T_ + (long)blockIdx.y * BM * T_;
    const __half* Bp = g_Vt + (long)z * DH_ * T_;
    __half* C = g_ao + ((long)b * T_ + blockIdx.y * BM) * D_ + h * DH_;
    gemm_nt<false, false, false>(A, Bp, C, T_, T_, T_, D_, 1.0f);
}

// 6) y = attn_out(fp16) @ W_proj(fp32)^T (fp32 out)
__global__ void k_proj(const float* __restrict__ wproj, float* __restrict__ out)
{
    const __half* A = g_ao + (long)blockIdx.y * BM * D_;
    const float* Bp = wproj + (long)blockIdx.x * BN * D_;
    float* C = out + (long)blockIdx.y * BM * D_ + blockIdx.x * BN;
    gemm_nt<false, true, true>(A, Bp, C, D_, D_, D_, D_, 1.0f);
}

// ---------------------------------------------------------------------------
extern "C" void kernel_launch(void* const* d_in, const int* in_sizes, int n_in,
                              void* d_out, int out_size)
{
    const float* x      = (const float*)d_in[0];   // [8,1024,1024]
    const float* w_qkv  = (const float*)d_in[1];   // [3072,1024]
    const float* w_proj = (const float*)d_in[2];   // [1024,1024]
    float* out = (float*)d_out;                    // [8,1024,1024]

    k_qkv    <<<dim3(D3 / BN, BT / BM), 256>>>(x, w_qkv);
    k_scores <<<dim3(T_ / BN, T_ / BM, B_ * H_), 256>>>();
    k_softmax<<<B_ * H_ * T_, 256>>>();
    k_transP <<<dim3(16, 16, B_ * H_), 256>>>();
    k_transV <<<dim3(16, B_ * H_), 256>>>();
    k_attnv  <<<dim3(1, T_ / BM, B_ * H_), 256>>>();
    k_proj   <<<dim3(D_ / BN, BT / BM), 256>>>(w_proj, out);
}

// round 5
// speedup vs baseline: 4.7116x; 1.4277x over previous
#include <cuda_runtime.h>
#include <cuda_fp16.h>

// Problem constants
#define B_  8
#define T_  1024
#define D_  1024
#define H_  16
#define DH_ 64
#define BT  (B_*T_)        // 8192
#define D3  (3*D_)         // 3072

// Dense GEMM tiling (qkv / proj)
#define BM 128
#define BN 64
#define BK 32
#define KS 40              // smem row stride in halves (32 + 8 pad)

#define LS 72              // attention smem row stride in halves (64 + 8 pad)

typedef unsigned int u32;

// Scratch (__device__ globals, allocation-free)
static __device__ __half g_qkv[(long)BT * D3];   // [t][3D] fp16, 48MB
static __device__ float  g_Z[(long)B_*H_*T_];    // softmax denominators, 512KB
static __device__ __half g_ao[(long)BT * D_];    // [t][D] fp16, 16MB

// ---------------------------------------------------------------------------
// PTX helpers
// ---------------------------------------------------------------------------
__device__ __forceinline__ u32 smem_u32(const void* p) {
    return (u32)__cvta_generic_to_shared(p);
}
__device__ __forceinline__ void ldsm_x4(u32& r0, u32& r1, u32& r2, u32& r3, u32 a) {
    asm volatile("ldmatrix.sync.aligned.m8n8.x4.shared.b16 {%0,%1,%2,%3},[%4];"
                 : "=r"(r0), "=r"(r1), "=r"(r2), "=r"(r3) : "r"(a));
}
__device__ __forceinline__ void ldsm_x2(u32& r0, u32& r1, u32 a) {
    asm volatile("ldmatrix.sync.aligned.m8n8.x2.shared.b16 {%0,%1},[%2];"
                 : "=r"(r0), "=r"(r1) : "r"(a));
}
__device__ __forceinline__ void ldsm_x2t(u32& r0, u32& r1, u32 a) {
    asm volatile("ldmatrix.sync.aligned.m8n8.x2.trans.shared.b16 {%0,%1},[%2];"
                 : "=r"(r0), "=r"(r1) : "r"(a));
}
__device__ __forceinline__ void mma16816(float c[4],
                                         u32 a0, u32 a1, u32 a2, u32 a3,
                                         u32 b0, u32 b1) {
    asm volatile("mma.sync.aligned.m16n8k16.row.col.f32.f16.f16.f32 "
                 "{%0,%1,%2,%3},{%4,%5,%6,%7},{%8,%9},{%0,%1,%2,%3};"
                 : "+f"(c[0]), "+f"(c[1]), "+f"(c[2]), "+f"(c[3])
                 : "r"(a0), "r"(a1), "r"(a2), "r"(a3), "r"(b0), "r"(b1));
}

// ===========================================================================
// Dense NT GEMM (for qkv and proj) — unchanged from R3
// ===========================================================================
__device__ __forceinline__ void load_tile_f32(const float* __restrict__ A, long lda,
                                              __half* As, int rows, int k0) {
    const int t = threadIdx.x;
    const int r_ = t >> 3, c_ = (t & 7) * 4;
    for (int r0 = 0; r0 < rows; r0 += 32) {
        int r = r0 + r_;
        float4 v = *(const float4*)(A + (long)r * lda + k0 + c_);
        __half2* dst = (__half2*)(&As[r * KS + c_]);
        dst[0] = __floats2half2_rn(v.x, v.y);
        dst[1] = __floats2half2_rn(v.z, v.w);
    }
}
__device__ __forceinline__ void load_tile_f16(const __half* __restrict__ A, long lda,
                                              __half* As, int rows, int k0) {
    const int t = threadIdx.x;
    const int r_ = t >> 2, c_ = (t & 3) * 8;
    for (int r0 = 0; r0 < rows; r0 += 64) {
        int r = r0 + r_;
        *(uint4*)(&As[r * KS + c_]) = *(const uint4*)(A + (long)r * lda + k0 + c_);
    }
}

template<bool AF32, bool BF32, bool CF32>
__device__ __forceinline__ void gemm_nt(const void* Ap, const void* Bp, void* Cp,
                                        int K, long lda, long ldb, long ldc, float alpha)
{
    __shared__ __half As[BM * KS];
    __shared__ __half Bs[BN * KS];

    const int t = threadIdx.x;
    const int warp = t >> 5, lane = t & 31;
    const int wm = warp >> 1, wn = warp & 1;

    float acc[2][4][4];
#pragma unroll
    for (int i = 0; i < 2; ++i)
#pragma unroll
        for (int j = 0; j < 4; ++j)
#pragma unroll
            for (int k = 0; k < 4; ++k) acc[i][j][k] = 0.0f;

    const u32 a_base = smem_u32(&As[(wm * 32 + (lane & 15)) * KS + (lane >> 4) * 8]);
    const u32 b_base = smem_u32(&Bs[(wn * 32 + (lane & 7)) * KS + ((lane >> 3) & 1) * 8]);

    for (int k0 = 0; k0 < K; k0 += BK) {
        if (AF32) load_tile_f32((const float*)Ap, lda, As, BM, k0);
        else      load_tile_f16((const __half*)Ap, lda, As, BM, k0);
        if (BF32) load_tile_f32((const float*)Bp, ldb, Bs, BN, k0);
        else      load_tile_f16((const __half*)Bp, ldb, Bs, BN, k0);
        __syncthreads();

#pragma unroll
        for (int ks = 0; ks < 2; ++ks) {
            u32 a[2][4], b[4][2];
#pragma unroll
            for (int mi = 0; mi < 2; ++mi)
                ldsm_x4(a[mi][0], a[mi][1], a[mi][2], a[mi][3],
                        a_base + (u32)((mi * 16 * KS + ks * 16) * 2));
#pragma unroll
            for (int ni = 0; ni < 4; ++ni)
                ldsm_x2(b[ni][0], b[ni][1],
                        b_base + (u32)((ni * 8 * KS + ks * 16) * 2));
#pragma unroll
            for (int mi = 0; mi < 2; ++mi)
#pragma unroll
                for (int ni = 0; ni < 4; ++ni)
                    mma16816(acc[mi][ni], a[mi][0], a[mi][1], a[mi][2], a[mi][3],
                             b[ni][0], b[ni][1]);
        }
        __syncthreads();
    }

    const int g = lane >> 2, tq = lane & 3;
#pragma unroll
    for (int mi = 0; mi < 2; ++mi) {
#pragma unroll
        for (int ni = 0; ni < 4; ++ni) {
            int row = wm * 32 + mi * 16 + g;
            int col = wn * 32 + ni * 8 + tq * 2;
            float v0 = acc[mi][ni][0] * alpha, v1 = acc[mi][ni][1] * alpha;
            float v2 = acc[mi][ni][2] * alpha, v3 = acc[mi][ni][3] * alpha;
            if (CF32) {
                float* C = (float*)Cp;
                *(float2*)(C + (long)row * ldc + col)       = make_float2(v0, v1);
                *(float2*)(C + (long)(row + 8) * ldc + col) = make_float2(v2, v3);
            } else {
                __half* C = (__half*)Cp;
                *(__half2*)(C + (long)row * ldc + col)       = __floats2half2_rn(v0, v1);
                *(__half2*)(C + (long)(row + 8) * ldc + col) = __floats2half2_rn(v2, v3);
            }
        }
    }
}

// 1) qkv(fp16) = x(fp32) @ W_qkv(fp32)^T : [8192,3072]
__global__ void k_qkv(const float* __restrict__ x, const float* __restrict__ w)
{
    const float* A = x + (long)blockIdx.y * BM * D_;
    const float* Bp = w + (long)blockIdx.x * BN * D_;
    __half* C = g_qkv + (long)blockIdx.y * BM * D3 + blockIdx.x * BN;
    gemm_nt<true, true, false>(A, Bp, C, D_, D_, D_, D3, 1.0f);
}

// ===========================================================================
// 2) k_zsum: Z[k] = sum_q exp(scale * K[k]·Q[q])   per (b,h)
//    Block: (kchunk of 128, bh). 8 warps, warp w owns k-rows [w*16, w*16+16).
// ===========================================================================
__global__ void k_zsum()
{
    __shared__ __align__(16) __half sK[128 * LS];
    __shared__ __align__(16) __half sQ[64 * LS];

    const int kc = blockIdx.x, bh = blockIdx.y;
    const int b = bh >> 4, h = bh & 15;
    const int t = threadIdx.x;
    const int warp = t >> 5, lane = t & 31;

    // Load K chunk [128][64]
    {
        const __half* Kg = g_qkv + ((long)b * T_ + kc * 128) * D3 + D_ + h * DH_;
        const int r_ = t >> 3, c_ = (t & 7) * 8;
#pragma unroll
        for (int p = 0; p < 4; ++p) {
            int r = r_ + p * 32;
            *(uint4*)&sK[r * LS + c_] = *(const uint4*)(Kg + (long)r * D3 + c_);
        }
    }
    __syncthreads();

    // Extract K a-fragments (m16 x k64) for this warp
    u32 a[4][4];
    {
        const u32 abase = smem_u32(&sK[(warp * 16 + (lane & 15)) * LS + (lane >> 4) * 8]);
#pragma unroll
        for (int ks = 0; ks < 4; ++ks)
            ldsm_x4(a[ks][0], a[ks][1], a[ks][2], a[ks][3], abase + (u32)(ks * 16 * 2));
    }

    float zacc0 = 0.0f, zacc1 = 0.0f;
    const __half* Qg = g_qkv + (long)b * T_ * D3 + h * DH_;
    const u32 bqbase = smem_u32(&sQ[(lane & 7) * LS + ((lane >> 3) & 1) * 8]);
    const int r2 = t >> 2, c2 = (t & 3) * 8;

    for (int qt = 0; qt < 16; ++qt) {
        __syncthreads();
        // Load Q tile [64][64]
        const __half* Qsrc = Qg + (long)(qt * 64 + r2) * D3;
        *(uint4*)&sQ[r2 * LS + c2]      = *(const uint4*)(Qsrc + c2);
        *(uint4*)&sQ[r2 * LS + c2 + 32] = *(const uint4*)(Qsrc + c2 + 32);
        __syncthreads();

        float c[8][4];
#pragma unroll
        for (int ni = 0; ni < 8; ++ni)
#pragma unroll
            for (int j = 0; j < 4; ++j) c[ni][j] = 0.0f;

#pragma unroll
        for (int ks = 0; ks < 4; ++ks) {
            u32 bq[8][2];
#pragma unroll
            for (int ni = 0; ni < 8; ++ni)
                ldsm_x2(bq[ni][0], bq[ni][1],
                        bqbase + (u32)((ni * 8 * LS + ks * 16) * 2));
#pragma unroll
            for (int ni = 0; ni < 8; ++ni)
                mma16816(c[ni], a[ks][0], a[ks][1], a[ks][2], a[ks][3],
                         bq[ni][0], bq[ni][1]);
        }

#pragma unroll
        for (int ni = 0; ni < 8; ++ni) {
            zacc0 += __expf(0.125f * c[ni][0]) + __expf(0.125f * c[ni][1]);
            zacc1 += __expf(0.125f * c[ni][2]) + __expf(0.125f * c[ni][3]);
        }
    }

    // Reduce over the 4 lanes sharing a row (tq = lane&3)
    zacc0 += __shfl_xor_sync(0xffffffffu, zacc0, 1);
    zacc0 += __shfl_xor_sync(0xffffffffu, zacc0, 2);
    zacc1 += __shfl_xor_sync(0xffffffffu, zacc1, 1);
    zacc1 += __shfl_xor_sync(0xffffffffu, zacc1, 2);
    if ((lane & 3) == 0) {
        int krow = kc * 128 + warp * 16 + (lane >> 2);
        g_Z[(long)bh * T_ + krow]     = zacc0;
        g_Z[(long)bh * T_ + krow + 8] = zacc1;
    }
}

// ===========================================================================
// 3) k_attn: fused attention. out[q,d] = sum_k exp(scale*q·k)/Z[k] * V[k,d]
//    Block: (qtile of 128, bh). Warp w owns q-rows [w*16, w*16+16).
// ===========================================================================
__global__ void k_attn()
{
    __shared__ __align__(16) __half sP[128 * LS];   // also Q staging initially
    __shared__ __align__(16) __half sK[64 * LS];
    __shared__ __align__(16) __half sV[64 * LS];
    __shared__ float sRZ[64];

    const int qt = blockIdx.x, bh = blockIdx.y;
    const int b = bh >> 4, h = bh & 15;
    const int t = threadIdx.x;
    const int warp = t >> 5, lane = t & 31;
    const int g = lane >> 2, tq = lane & 3;

    // Load Q tile [128][64] into sP staging
    {
        const __half* Qg = g_qkv + ((long)b * T_ + qt * 128) * D3 + h * DH_;
        const int r_ = t >> 3, c_ = (t & 7) * 8;
#pragma unroll
        for (int p = 0; p < 4; ++p) {
            int r = r_ + p * 32;
            *(uint4*)&sP[r * LS + c_] = *(const uint4*)(Qg + (long)r * D3 + c_);
        }
    }
    __syncthreads();

    // Extract Q a-fragments (m16 x k64)
    u32 aq[4][4];
    const u32 pbase = smem_u32(&sP[(warp * 16 + (lane & 15)) * LS + (lane >> 4) * 8]);
#pragma unroll
    for (int ks = 0; ks < 4; ++ks)
        ldsm_x4(aq[ks][0], aq[ks][1], aq[ks][2], aq[ks][3], pbase + (u32)(ks * 16 * 2));

    float o[8][4];
#pragma unroll
    for (int ni = 0; ni < 8; ++ni)
#pragma unroll
        for (int j = 0; j < 4; ++j) o[ni][j] = 0.0f;

    const __half* Kg = g_qkv + (long)b * T_ * D3 + D_ + h * DH_;
    const __half* Vg = g_qkv + (long)b * T_ * D3 + 2 * D_ + h * DH_;
    const float* Zp = g_Z + (long)bh * T_;
    const u32 bkbase = smem_u32(&sK[(lane & 7) * LS + ((lane >> 3) & 1) * 8]);
    const u32 bvbase = smem_u32(&sV[(lane & 15) * LS]);
    const int r2 = t >> 2, c2 = (t & 3) * 8;

    for (int kc = 0; kc < 16; ++kc) {
        __syncthreads();
        // Load K,V chunk [64][64] each + reciprocal Z
        {
            const __half* Ksrc = Kg + (long)(kc * 64 + r2) * D3;
            const __half* Vsrc = Vg + (long)(kc * 64 + r2) * D3;
            *(uint4*)&sK[r2 * LS + c2]      = *(const uint4*)(Ksrc + c2);
            *(uint4*)&sK[r2 * LS + c2 + 32] = *(const uint4*)(Ksrc + c2 + 32);
            *(uint4*)&sV[r2 * LS + c2]      = *(const uint4*)(Vsrc + c2);
            *(uint4*)&sV[r2 * LS + c2 + 32] = *(const uint4*)(Vsrc + c2 + 32);
            if (t < 64) sRZ[t] = 1.0f / Zp[kc * 64 + t];
        }
        __syncthreads();

        // S tile: [q m16][k n64] = Q·K^T
        float c[8][4];
#pragma unroll
        for (int ni = 0; ni < 8; ++ni)
#pragma unroll
            for (int j = 0; j < 4; ++j) c[ni][j] = 0.0f;

#pragma unroll
        for (int ks = 0; ks < 4; ++ks) {
            u32 bk[8][2];
#pragma unroll
            for (int ni = 0; ni < 8; ++ni)
                ldsm_x2(bk[ni][0], bk[ni][1],
                        bkbase + (u32)((ni * 8 * LS + ks * 16) * 2));
#pragma unroll
            for (int ni = 0; ni < 8; ++ni)
                mma16816(c[ni], aq[ks][0], aq[ks][1], aq[ks][2], aq[ks][3],
                         bk[ni][0], bk[ni][1]);
        }

        // p = exp(scale*s) / Z[k], write fp16 P tile to smem
#pragma unroll
        for (int ni = 0; ni < 8; ++ni) {
            int col = ni * 8 + tq * 2;
            float rz0 = sRZ[col], rz1 = sRZ[col + 1];
            __half2 p01 = __floats2half2_rn(__expf(0.125f * c[ni][0]) * rz0,
                                            __expf(0.125f * c[ni][1]) * rz1);
            __half2 p23 = __floats2half2_rn(__expf(0.125f * c[ni][2]) * rz0,
                                            __expf(0.125f * c[ni][3]) * rz1);
            *(__half2*)&sP[(warp * 16 + g) * LS + col]     = p01;
            *(__half2*)&sP[(warp * 16 + g + 8) * LS + col] = p23;
        }
        __syncthreads();

        // O += P·V : A = P [q m16][k], B = V [k][d] via ldmatrix.trans
#pragma unroll
        for (int ks = 0; ks < 4; ++ks) {
            u32 ap[4];
            ldsm_x4(ap[0], ap[1], ap[2], ap[3], pbase + (u32)(ks * 16 * 2));
            u32 bv[8][2];
#pragma unroll
            for (int nd = 0; nd < 8; ++nd)
                ldsm_x2t(bv[nd][0], bv[nd][1],
                         bvbase + (u32)((ks * 16 * LS + nd * 8) * 2));
#pragma unroll
            for (int nd = 0; nd < 8; ++nd)
                mma16816(o[nd], ap[0], ap[1], ap[2], ap[3], bv[nd][0], bv[nd][1]);
        }
    }

    // Epilogue: write fp16 attention output
    __half* Og = g_ao + ((long)b * T_ + qt * 128) * D_ + h * DH_;
#pragma unroll
    for (int nd = 0; nd < 8; ++nd) {
        int row = warp * 16 + g;
        int col = nd * 8 + tq * 2;
        *(__half2*)(Og + (long)row * D_ + col)       = __floats2half2_rn(o[nd][0], o[nd][1]);
        *(__half2*)(Og + (long)(row + 8) * D_ + col) = __floats2half2_rn(o[nd][2], o[nd][3]);
    }
}

// 4) y = attn_out(fp16) @ W_proj(fp32)^T (fp32 out)
__global__ void k_proj(const float* __restrict__ wproj, float* __restrict__ out)
{
    const __half* A = g_ao + (long)blockIdx.y * BM * D_;
    const float* Bp = wproj + (long)blockIdx.x * BN * D_;
    float* C = out + (long)blockIdx.y * BM * D_ + blockIdx.x * BN;
    gemm_nt<false, true, true>(A, Bp, C, D_, D_, D_, D_, 1.0f);
}

// ---------------------------------------------------------------------------
extern "C" void kernel_launch(void* const* d_in, const int* in_sizes, int n_in,
                              void* d_out, int out_size)
{
    const float* x      = (const float*)d_in[0];   // [8,1024,1024]
    const float* w_qkv  = (const float*)d_in[1];   // [3072,1024]
    const float* w_proj = (const float*)d_in[2];   // [1024,1024]
    float* out = (float*)d_out;                    // [8,1024,1024]

    k_qkv <<<dim3(D3 / BN, BT / BM), 256>>>(x, w_qkv);
    k_zsum<<<dim3(T_ / 128, B_ * H_), 256>>>();
    k_attn<<<dim3(T_ / 128, B_ * H_), 256>>>();
    k_proj<<<dim3(D_ / BN, BT / BM), 256>>>(w_proj, out);
}

// round 8
// speedup vs baseline: 5.2569x; 1.1157x over previous
#include <cuda_runtime.h>
#include <cuda_fp16.h>

// Problem constants
#define B_  8
#define T_  1024
#define D_  1024
#define H_  16
#define DH_ 64
#define BT  (B_*T_)        // 8192
#define D3  (3*D_)         // 3072

#define KSD 40             // dense gemm smem row stride (32 + 8 pad), halves
#define LS 72              // attention smem row stride (64 + 8 pad), halves

typedef unsigned int u32;

// Scratch (__device__ globals — referenced ONLY from device code!)
static __device__ __half g_x16[(long)BT * D_];       // x fp16, 16MB
static __device__ __half g_wqkv16[(long)D3 * D_];    // W_qkv fp16, 6MB
static __device__ __half g_wproj16[(long)D_ * D_];   // W_proj fp16, 2MB
static __device__ __half g_qkv[(long)BT * D3];       // [t][3D] fp16, 48MB
static __device__ float  g_Z[(long)B_*H_*T_];        // softmax denominators
static __device__ __half g_ao[(long)BT * D_];        // [t][D] fp16, 16MB

// ---------------------------------------------------------------------------
// PTX helpers
// ---------------------------------------------------------------------------
__device__ __forceinline__ u32 smem_u32(const void* p) {
    return (u32)__cvta_generic_to_shared(p);
}
__device__ __forceinline__ void ldsm_x4(u32& r0, u32& r1, u32& r2, u32& r3, u32 a) {
    asm volatile("ldmatrix.sync.aligned.m8n8.x4.shared.b16 {%0,%1,%2,%3},[%4];"
                 : "=r"(r0), "=r"(r1), "=r"(r2), "=r"(r3) : "r"(a));
}
__device__ __forceinline__ void ldsm_x2(u32& r0, u32& r1, u32 a) {
    asm volatile("ldmatrix.sync.aligned.m8n8.x2.shared.b16 {%0,%1},[%2];"
                 : "=r"(r0), "=r"(r1) : "r"(a));
}
__device__ __forceinline__ void ldsm_x2t(u32& r0, u32& r1, u32 a) {
    asm volatile("ldmatrix.sync.aligned.m8n8.x2.trans.shared.b16 {%0,%1},[%2];"
                 : "=r"(r0), "=r"(r1) : "r"(a));
}
__device__ __forceinline__ void mma16816(float c[4],
                                         u32 a0, u32 a1, u32 a2, u32 a3,
                                         u32 b0, u32 b1) {
    asm volatile("mma.sync.aligned.m16n8k16.row.col.f32.f16.f16.f32 "
                 "{%0,%1,%2,%3},{%4,%5,%6,%7},{%8,%9},{%0,%1,%2,%3};"
                 : "+f"(c[0]), "+f"(c[1]), "+f"(c[2]), "+f"(c[3])
                 : "r"(a0), "r"(a1), "r"(a2), "r"(a3), "r"(b0), "r"(b1));
}

// ---------------------------------------------------------------------------
// fp32 -> fp16 conversion: dst is a device global, named in device code only.
// ---------------------------------------------------------------------------
__device__ __forceinline__ void f2h_body(const float* __restrict__ s, __half* __restrict__ d)
{
    long i = ((long)blockIdx.x * blockDim.x + threadIdx.x) * 8;
    float4 v0 = *(const float4*)(s + i);
    float4 v1 = *(const float4*)(s + i + 4);
    uint4 o;
    __half2* hp = (__half2*)&o;
    hp[0] = __floats2half2_rn(v0.x, v0.y);
    hp[1] = __floats2half2_rn(v0.z, v0.w);
    hp[2] = __floats2half2_rn(v1.x, v1.y);
    hp[3] = __floats2half2_rn(v1.z, v1.w);
    *(uint4*)(d + i) = o;
}
__global__ void k_f2h_x(const float* __restrict__ s)     { f2h_body(s, g_x16); }
__global__ void k_f2h_wqkv(const float* __restrict__ s)  { f2h_body(s, g_wqkv16); }
__global__ void k_f2h_wproj(const float* __restrict__ s) { f2h_body(s, g_wproj16); }

// ---------------------------------------------------------------------------
// Dense NT GEMM body: C[m,n] = sum_k A[m][k]*B[n][k]
// Tile 128x128x32, 256 threads = 8 warps (2 x 4), warp tile 64x32.
// Register double-buffering of gmem loads.
// ---------------------------------------------------------------------------
template<bool CF32>
__device__ __forceinline__ void gemm128_body(
    const __half* __restrict__ A, const __half* __restrict__ B, void* Cp,
    int K, long ldc)
{
    __shared__ __align__(16) __half sA[128 * KSD];
    __shared__ __align__(16) __half sB[128 * KSD];

    const int t = threadIdx.x;
    const int warp = t >> 5, lane = t & 31;
    const int wm = warp >> 2, wn = warp & 3;
    const long m0 = (long)blockIdx.y * 128, n0 = (long)blockIdx.x * 128;

    const int lr = t >> 2;          // 0..63
    const int lc = (t & 3) * 8;     // 0,8,16,24 halves

    const __half* Ag0 = A + (m0 + lr) * (long)K + lc;
    const __half* Ag1 = Ag0 + 64 * (long)K;
    const __half* Bg0 = B + (n0 + lr) * (long)K + lc;
    const __half* Bg1 = Bg0 + 64 * (long)K;

    uint4* stA0 = (uint4*)&sA[lr * KSD + lc];
    uint4* stA1 = (uint4*)&sA[(lr + 64) * KSD + lc];
    uint4* stB0 = (uint4*)&sB[lr * KSD + lc];
    uint4* stB1 = (uint4*)&sB[(lr + 64) * KSD + lc];

    uint4 ra0 = *(const uint4*)Ag0, ra1 = *(const uint4*)Ag1;
    uint4 rb0 = *(const uint4*)Bg0, rb1 = *(const uint4*)Bg1;

    float acc[4][4][4];
#pragma unroll
    for (int i = 0; i < 4; ++i)
#pragma unroll
        for (int j = 0; j < 4; ++j)
#pragma unroll
            for (int k = 0; k < 4; ++k) acc[i][j][k] = 0.0f;

    const u32 abase = smem_u32(&sA[(wm * 64 + (lane & 15)) * KSD + (lane >> 4) * 8]);
    const u32 bbase = smem_u32(&sB[(wn * 32 + (lane & 7)) * KSD + ((lane >> 3) & 1) * 8]);

    const int KT = K >> 5;
    for (int kt = 0; kt < KT; ++kt) {
        *stA0 = ra0; *stA1 = ra1;
        *stB0 = rb0; *stB1 = rb1;
        __syncthreads();

        if (kt + 1 < KT) {
            const long ko = (long)(kt + 1) * 32;
            ra0 = *(const uint4*)(Ag0 + ko);
            ra1 = *(const uint4*)(Ag1 + ko);
            rb0 = *(const uint4*)(Bg0 + ko);
            rb1 = *(const uint4*)(Bg1 + ko);
        }

#pragma unroll
        for (int ks = 0; ks < 2; ++ks) {
            u32 a[4][4], b[4][2];
#pragma unroll
            for (int mi = 0; mi < 4; ++mi)
                ldsm_x4(a[mi][0], a[mi][1], a[mi][2], a[mi][3],
                        abase + (u32)((mi * 16 * KSD + ks * 16) * 2));
#pragma unroll
            for (int ni = 0; ni < 4; ++ni)
                ldsm_x2(b[ni][0], b[ni][1],
                        bbase + (u32)((ni * 8 * KSD + ks * 16) * 2));
#pragma unroll
            for (int mi = 0; mi < 4; ++mi)
#pragma unroll
                for (int ni = 0; ni < 4; ++ni)
                    mma16816(acc[mi][ni], a[mi][0], a[mi][1], a[mi][2], a[mi][3],
                             b[ni][0], b[ni][1]);
        }
        __syncthreads();
    }

    const int g = lane >> 2, tq = lane & 3;
#pragma unroll
    for (int mi = 0; mi < 4; ++mi) {
#pragma unroll
        for (int ni = 0; ni < 4; ++ni) {
            long row = m0 + wm * 64 + mi * 16 + g;
            long col = n0 + wn * 32 + ni * 8 + tq * 2;
            if (CF32) {
                float* C = (float*)Cp;
                *(float2*)(C + row * ldc + col)       = make_float2(acc[mi][ni][0], acc[mi][ni][1]);
                *(float2*)(C + (row + 8) * ldc + col) = make_float2(acc[mi][ni][2], acc[mi][ni][3]);
            } else {
                __half* C = (__half*)Cp;
                *(__half2*)(C + row * ldc + col)       = __floats2half2_rn(acc[mi][ni][0], acc[mi][ni][1]);
                *(__half2*)(C + (row + 8) * ldc + col) = __floats2half2_rn(acc[mi][ni][2], acc[mi][ni][3]);
            }
        }
    }
}

// Wrappers: globals are named HERE, in device code.
__global__ void __launch_bounds__(256) k_qkv16()
{
    gemm128_body<false>(g_x16, g_wqkv16, g_qkv, D_, D3);
}
__global__ void __launch_bounds__(256) k_proj16(float* __restrict__ out)
{
    gemm128_body<true>(g_ao, g_wproj16, out, D_, D_);
}

// ===========================================================================
// k_zsum: Z[k] = sum_q exp(scale * K[k]·Q[q])   per (b,h)   [R4 verbatim]
// ===========================================================================
__global__ void k_zsum()
{
    __shared__ __align__(16) __half sK[128 * LS];
    __shared__ __align__(16) __half sQ[64 * LS];

    const int kc = blockIdx.x, bh = blockIdx.y;
    const int b = bh >> 4, h = bh & 15;
    const int t = threadIdx.x;
    const int warp = t >> 5, lane = t & 31;

    {
        const __half* Kg = g_qkv + ((long)b * T_ + kc * 128) * D3 + D_ + h * DH_;
        const int r_ = t >> 3, c_ = (t & 7) * 8;
#pragma unroll
        for (int p = 0; p < 4; ++p) {
            int r = r_ + p * 32;
            *(uint4*)&sK[r * LS + c_] = *(const uint4*)(Kg + (long)r * D3 + c_);
        }
    }
    __syncthreads();

    u32 a[4][4];
    {
        const u32 abase = smem_u32(&sK[(warp * 16 + (lane & 15)) * LS + (lane >> 4) * 8]);
#pragma unroll
        for (int ks = 0; ks < 4; ++ks)
            ldsm_x4(a[ks][0], a[ks][1], a[ks][2], a[ks][3], abase + (u32)(ks * 16 * 2));
    }

    float zacc0 = 0.0f, zacc1 = 0.0f;
    const __half* Qg = g_qkv + (long)b * T_ * D3 + h * DH_;
    const u32 bqbase = smem_u32(&sQ[(lane & 7) * LS + ((lane >> 3) & 1) * 8]);
    const int r2 = t >> 2, c2 = (t & 3) * 8;

    for (int qt = 0; qt < 16; ++qt) {
        __syncthreads();
        const __half* Qsrc = Qg + (long)(qt * 64 + r2) * D3;
        *(uint4*)&sQ[r2 * LS + c2]      = *(const uint4*)(Qsrc + c2);
        *(uint4*)&sQ[r2 * LS + c2 + 32] = *(const uint4*)(Qsrc + c2 + 32);
        __syncthreads();

        float c[8][4];
#pragma unroll
        for (int ni = 0; ni < 8; ++ni)
#pragma unroll
            for (int j = 0; j < 4; ++j) c[ni][j] = 0.0f;

#pragma unroll
        for (int ks = 0; ks < 4; ++ks) {
            u32 bq[8][2];
#pragma unroll
            for (int ni = 0; ni < 8; ++ni)
                ldsm_x2(bq[ni][0], bq[ni][1],
                        bqbase + (u32)((ni * 8 * LS + ks * 16) * 2));
#pragma unroll
            for (int ni = 0; ni < 8; ++ni)
                mma16816(c[ni], a[ks][0], a[ks][1], a[ks][2], a[ks][3],
                         bq[ni][0], bq[ni][1]);
        }

#pragma unroll
        for (int ni = 0; ni < 8; ++ni) {
            zacc0 += __expf(0.125f * c[ni][0]) + __expf(0.125f * c[ni][1]);
            zacc1 += __expf(0.125f * c[ni][2]) + __expf(0.125f * c[ni][3]);
        }
    }

    zacc0 += __shfl_xor_sync(0xffffffffu, zacc0, 1);
    zacc0 += __shfl_xor_sync(0xffffffffu, zacc0, 2);
    zacc1 += __shfl_xor_sync(0xffffffffu, zacc1, 1);
    zacc1 += __shfl_xor_sync(0xffffffffu, zacc1, 2);
    if ((lane & 3) == 0) {
        int krow = kc * 128 + warp * 16 + (lane >> 2);
        g_Z[(long)bh * T_ + krow]     = zacc0;
        g_Z[(long)bh * T_ + krow + 8] = zacc1;
    }
}

// ===========================================================================
// k_attn: out[q,d] = sum_k exp(scale*q·k)/Z[k] * V[k,d]     [R4 verbatim]
// ===========================================================================
__global__ void k_attn()
{
    __shared__ __align__(16) __half sP[128 * LS];
    __shared__ __align__(16) __half sK[64 * LS];
    __shared__ __align__(16) __half sV[64 * LS];
    __shared__ float sRZ[64];

    const int qt = blockIdx.x, bh = blockIdx.y;
    const int b = bh >> 4, h = bh & 15;
    const int t = threadIdx.x;
    const int warp = t >> 5, lane = t & 31;
    const int g = lane >> 2, tq = lane & 3;

    {
        const __half* Qg = g_qkv + ((long)b * T_ + qt * 128) * D3 + h * DH_;
        const int r_ = t >> 3, c_ = (t & 7) * 8;
#pragma unroll
        for (int p = 0; p < 4; ++p) {
            int r = r_ + p * 32;
            *(uint4*)&sP[r * LS + c_] = *(const uint4*)(Qg + (long)r * D3 + c_);
        }
    }
    __syncthreads();

    u32 aq[4][4];
    const u32 pbase = smem_u32(&sP[(warp * 16 + (lane & 15)) * LS + (lane >> 4) * 8]);
#pragma unroll
    for (int ks = 0; ks < 4; ++ks)
        ldsm_x4(aq[ks][0], aq[ks][1], aq[ks][2], aq[ks][3], pbase + (u32)(ks * 16 * 2));

    float o[8][4];
#pragma unroll
    for (int ni = 0; ni < 8; ++ni)
#pragma unroll
        for (int j = 0; j < 4; ++j) o[ni][j] = 0.0f;

    const __half* Kg = g_qkv + (long)b * T_ * D3 + D_ + h * DH_;
    const __half* Vg = g_qkv + (long)b * T_ * D3 + 2 * D_ + h * DH_;
    const float* Zp = g_Z + (long)bh * T_;
    const u32 bkbase = smem_u32(&sK[(lane & 7) * LS + ((lane >> 3) & 1) * 8]);
    const u32 bvbase = smem_u32(&sV[(lane & 15) * LS]);
    const int r2 = t >> 2, c2 = (t & 3) * 8;

    for (int kc = 0; kc < 16; ++kc) {
        __syncthreads();
        {
            const __half* Ksrc = Kg + (long)(kc * 64 + r2) * D3;
            const __half* Vsrc = Vg + (long)(kc * 64 + r2) * D3;
            *(uint4*)&sK[r2 * LS + c2]      = *(const uint4*)(Ksrc + c2);
            *(uint4*)&sK[r2 * LS + c2 + 32] = *(const uint4*)(Ksrc + c2 + 32);
            *(uint4*)&sV[r2 * LS + c2]      = *(const uint4*)(Vsrc + c2);
            *(uint4*)&sV[r2 * LS + c2 + 32] = *(const uint4*)(Vsrc + c2 + 32);
            if (t < 64) sRZ[t] = 1.0f / Zp[kc * 64 + t];
        }
        __syncthreads();

        float c[8][4];
#pragma unroll
        for (int ni = 0; ni < 8; ++ni)
#pragma unroll
            for (int j = 0; j < 4; ++j) c[ni][j] = 0.0f;

#pragma unroll
        for (int ks = 0; ks < 4; ++ks) {
            u32 bk[8][2];
#pragma unroll
            for (int ni = 0; ni < 8; ++ni)
                ldsm_x2(bk[ni][0], bk[ni][1],
                        bkbase + (u32)((ni * 8 * LS + ks * 16) * 2));
#pragma unroll
            for (int ni = 0; ni < 8; ++ni)
                mma16816(c[ni], aq[ks][0], aq[ks][1], aq[ks][2], aq[ks][3],
                         bk[ni][0], bk[ni][1]);
        }

#pragma unroll
        for (int ni = 0; ni < 8; ++ni) {
            int col = ni * 8 + tq * 2;
            float rz0 = sRZ[col], rz1 = sRZ[col + 1];
            __half2 p01 = __floats2half2_rn(__expf(0.125f * c[ni][0]) * rz0,
                                            __expf(0.125f * c[ni][1]) * rz1);
            __half2 p23 = __floats2half2_rn(__expf(0.125f * c[ni][2]) * rz0,
                                            __expf(0.125f * c[ni][3]) * rz1);
            *(__half2*)&sP[(warp * 16 + g) * LS + col]     = p01;
            *(__half2*)&sP[(warp * 16 + g + 8) * LS + col] = p23;
        }
        __syncthreads();

#pragma unroll
        for (int ks = 0; ks < 4; ++ks) {
            u32 ap[4];
            ldsm_x4(ap[0], ap[1], ap[2], ap[3], pbase + (u32)(ks * 16 * 2));
            u32 bv[8][2];
#pragma unroll
            for (int nd = 0; nd < 8; ++nd)
                ldsm_x2t(bv[nd][0], bv[nd][1],
                         bvbase + (u32)((ks * 16 * LS + nd * 8) * 2));
#pragma unroll
            for (int nd = 0; nd < 8; ++nd)
                mma16816(o[nd], ap[0], ap[1], ap[2], ap[3], bv[nd][0], bv[nd][1]);
        }
    }

    __half* Og = g_ao + ((long)b * T_ + qt * 128) * D_ + h * DH_;
#pragma unroll
    for (int nd = 0; nd < 8; ++nd) {
        int row = warp * 16 + g;
        int col = nd * 8 + tq * 2;
        *(__half2*)(Og + (long)row * D_ + col)       = __floats2half2_rn(o[nd][0], o[nd][1]);
        *(__half2*)(Og + (long)(row + 8) * D_ + col) = __floats2half2_rn(o[nd][2], o[nd][3]);
    }
}

// ---------------------------------------------------------------------------
extern "C" void kernel_launch(void* const* d_in, const int* in_sizes, int n_in,
                              void* d_out, int out_size)
{
    const float* x      = (const float*)d_in[0];   // [8,1024,1024]
    const float* w_qkv  = (const float*)d_in[1];   // [3072,1024]
    const float* w_proj = (const float*)d_in[2];   // [1024,1024]
    float* out = (float*)d_out;                    // [8,1024,1024]

    k_f2h_x    <<<(long)BT * D_ / 2048, 256>>>(x);
    k_f2h_wqkv <<<(long)D3 * D_ / 2048, 256>>>(w_qkv);
    k_f2h_wproj<<<(long)D_ * D_ / 2048, 256>>>(w_proj);

    k_qkv16 <<<dim3(D3 / 128, BT / 128), 256>>>();
    k_zsum  <<<dim3(T_ / 128, B_ * H_), 256>>>();
    k_attn  <<<dim3(T_ / 128, B_ * H_), 256>>>();
    k_proj16<<<dim3(D_ / 128, BT / 128), 256>>>(out);
}

// round 9
// speedup vs baseline: 6.1458x; 1.1691x over previous
#include <cuda_runtime.h>
#include <cuda_fp16.h>

// Problem constants
#define B_  8
#define T_  1024
#define D_  1024
#define H_  16
#define DH_ 64
#define BT  (B_*T_)        // 8192
#define D3  (3*D_)         // 3072

#define KSD 40             // dense gemm smem row stride (32 + 8 pad), halves; 80B = 16B-aligned
#define LS 72              // attention smem row stride (64 + 8 pad), halves

typedef unsigned int u32;

// Scratch (__device__ globals — referenced ONLY from device code!)
static __device__ __half g_x16[(long)BT * D_];       // x fp16, 16MB
static __device__ __half g_wqkv16[(long)D3 * D_];    // W_qkv fp16, 6MB
static __device__ __half g_wproj16[(long)D_ * D_];   // W_proj fp16, 2MB
static __device__ __half g_qkv[(long)BT * D3];       // [t][3D] fp16, 48MB
static __device__ float  g_Z[(long)B_*H_*T_];        // softmax denominators
static __device__ __half g_ao[(long)BT * D_];        // [t][D] fp16, 16MB

// ---------------------------------------------------------------------------
// PTX helpers
// ---------------------------------------------------------------------------
__device__ __forceinline__ u32 smem_u32(const void* p) {
    return (u32)__cvta_generic_to_shared(p);
}
__device__ __forceinline__ void ldsm_x4(u32& r0, u32& r1, u32& r2, u32& r3, u32 a) {
    asm volatile("ldmatrix.sync.aligned.m8n8.x4.shared.b16 {%0,%1,%2,%3},[%4];"
                 : "=r"(r0), "=r"(r1), "=r"(r2), "=r"(r3) : "r"(a));
}
__device__ __forceinline__ void ldsm_x2(u32& r0, u32& r1, u32 a) {
    asm volatile("ldmatrix.sync.aligned.m8n8.x2.shared.b16 {%0,%1},[%2];"
                 : "=r"(r0), "=r"(r1) : "r"(a));
}
__device__ __forceinline__ void ldsm_x2t(u32& r0, u32& r1, u32 a) {
    asm volatile("ldmatrix.sync.aligned.m8n8.x2.trans.shared.b16 {%0,%1},[%2];"
                 : "=r"(r0), "=r"(r1) : "r"(a));
}
__device__ __forceinline__ void mma16816(float c[4],
                                         u32 a0, u32 a1, u32 a2, u32 a3,
                                         u32 b0, u32 b1) {
    asm volatile("mma.sync.aligned.m16n8k16.row.col.f32.f16.f16.f32 "
                 "{%0,%1,%2,%3},{%4,%5,%6,%7},{%8,%9},{%0,%1,%2,%3};"
                 : "+f"(c[0]), "+f"(c[1]), "+f"(c[2]), "+f"(c[3])
                 : "r"(a0), "r"(a1), "r"(a2), "r"(a3), "r"(b0), "r"(b1));
}
__device__ __forceinline__ void cpa16(u32 dst, const void* src) {
    asm volatile("cp.async.cg.shared.global [%0],[%1],16;" :: "r"(dst), "l"(src));
}
#define CP_COMMIT() asm volatile("cp.async.commit_group;")
#define CP_WAIT0()  asm volatile("cp.async.wait_group 0;")

// ---------------------------------------------------------------------------
// fp32 -> fp16 conversion (globals named in device code only)
// ---------------------------------------------------------------------------
__device__ __forceinline__ void f2h_body(const float* __restrict__ s, __half* __restrict__ d)
{
    long i = ((long)blockIdx.x * blockDim.x + threadIdx.x) * 8;
    float4 v0 = *(const float4*)(s + i);
    float4 v1 = *(const float4*)(s + i + 4);
    uint4 o;
    __half2* hp = (__half2*)&o;
    hp[0] = __floats2half2_rn(v0.x, v0.y);
    hp[1] = __floats2half2_rn(v0.z, v0.w);
    hp[2] = __floats2half2_rn(v1.x, v1.y);
    hp[3] = __floats2half2_rn(v1.z, v1.w);
    *(uint4*)(d + i) = o;
}
__global__ void k_f2h_x(const float* __restrict__ s)     { f2h_body(s, g_x16); }
__global__ void k_f2h_wqkv(const float* __restrict__ s)  { f2h_body(s, g_wqkv16); }
__global__ void k_f2h_wproj(const float* __restrict__ s) { f2h_body(s, g_wproj16); }

// ---------------------------------------------------------------------------
// Dense NT GEMM body: C[m,n] = sum_k A[m][k]*B[n][k]
// Tile 128x128x32, 256 threads = 8 warps (2 x 4), warp tile 64x32.
// cp.async 2-stage double buffering (R5 loop structure, R7-proven fragments).
// ---------------------------------------------------------------------------
template<bool CF32>
__device__ __forceinline__ void gemm128_body(
    const __half* __restrict__ A, const __half* __restrict__ B, void* Cp,
    int K, long ldc)
{
    __shared__ __align__(16) __half sA[2][128 * KSD];
    __shared__ __align__(16) __half sB[2][128 * KSD];

    const int t = threadIdx.x;
    const int warp = t >> 5, lane = t & 31;
    const int wm = warp >> 2, wn = warp & 3;
    const long m0 = (long)blockIdx.y * 128, n0 = (long)blockIdx.x * 128;

    const int lr = t >> 2;          // 0..63
    const int lc = (t & 3) * 8;     // 0,8,16,24 halves

    const __half* Ag0 = A + (m0 + lr) * (long)K + lc;
    const __half* Ag1 = Ag0 + 64 * (long)K;
    const __half* Bg0 = B + (n0 + lr) * (long)K + lc;
    const __half* Bg1 = Bg0 + 64 * (long)K;

    const u32 dA0 = smem_u32(&sA[0][lr * KSD + lc]);
    const u32 dA1 = smem_u32(&sA[0][(lr + 64) * KSD + lc]);
    const u32 dB0 = smem_u32(&sB[0][lr * KSD + lc]);
    const u32 dB1 = smem_u32(&sB[0][(lr + 64) * KSD + lc]);
    const u32 SBY = (u32)sizeof(sA[0]);   // stage size in bytes

    // prologue: tile 0 -> stage 0
    cpa16(dA0, Ag0); cpa16(dA1, Ag1);
    cpa16(dB0, Bg0); cpa16(dB1, Bg1);
    CP_COMMIT();

    float acc[4][4][4];
#pragma unroll
    for (int i = 0; i < 4; ++i)
#pragma unroll
        for (int j = 0; j < 4; ++j)
#pragma unroll
            for (int k = 0; k < 4; ++k) acc[i][j][k] = 0.0f;

    const u32 abase = smem_u32(&sA[0][(wm * 64 + (lane & 15)) * KSD + (lane >> 4) * 8]);
    const u32 bbase = smem_u32(&sB[0][(wn * 32 + (lane & 7)) * KSD + ((lane >> 3) & 1) * 8]);

    const int KT = K >> 5;
    for (int kt = 0; kt < KT; ++kt) {
        CP_WAIT0();
        __syncthreads();
        const int st = kt & 1;

        // Issue next tile into the other stage (overlaps with MMA below)
        if (kt + 1 < KT) {
            const long ko = (long)(kt + 1) * 32;
            const u32 o = (u32)(st ^ 1) * SBY;
            cpa16(dA0 + o, Ag0 + ko); cpa16(dA1 + o, Ag1 + ko);
            cpa16(dB0 + o, Bg0 + ko); cpa16(dB1 + o, Bg1 + ko);
        }
        CP_COMMIT();

        const u32 ab = abase + (u32)st * SBY;
        const u32 bb = bbase + (u32)st * SBY;
#pragma unroll
        for (int ks = 0; ks < 2; ++ks) {
            u32 a[4][4], b[4][2];
#pragma unroll
            for (int mi = 0; mi < 4; ++mi)
                ldsm_x4(a[mi][0], a[mi][1], a[mi][2], a[mi][3],
                        ab + (u32)((mi * 16 * KSD + ks * 16) * 2));
#pragma unroll
            for (int ni = 0; ni < 4; ++ni)
                ldsm_x2(b[ni][0], b[ni][1],
                        bb + (u32)((ni * 8 * KSD + ks * 16) * 2));
#pragma unroll
            for (int mi = 0; mi < 4; ++mi)
#pragma unroll
                for (int ni = 0; ni < 4; ++ni)
                    mma16816(acc[mi][ni], a[mi][0], a[mi][1], a[mi][2], a[mi][3],
                             b[ni][0], b[ni][1]);
        }
    }

    const int g = lane >> 2, tq = lane & 3;
#pragma unroll
    for (int mi = 0; mi < 4; ++mi) {
#pragma unroll
        for (int ni = 0; ni < 4; ++ni) {
            long row = m0 + wm * 64 + mi * 16 + g;
            long col = n0 + wn * 32 + ni * 8 + tq * 2;
            if (CF32) {
                float* C = (float*)Cp;
                *(float2*)(C + row * ldc + col)       = make_float2(acc[mi][ni][0], acc[mi][ni][1]);
                *(float2*)(C + (row + 8) * ldc + col) = make_float2(acc[mi][ni][2], acc[mi][ni][3]);
            } else {
                __half* C = (__half*)Cp;
                *(__half2*)(C + row * ldc + col)       = __floats2half2_rn(acc[mi][ni][0], acc[mi][ni][1]);
                *(__half2*)(C + (row + 8) * ldc + col) = __floats2half2_rn(acc[mi][ni][2], acc[mi][ni][3]);
            }
        }
    }
}

// Wrappers: globals are named HERE, in device code.
__global__ void __launch_bounds__(256, 2) k_qkv16()
{
    gemm128_body<false>(g_x16, g_wqkv16, g_qkv, D_, D3);
}
__global__ void __launch_bounds__(256, 2) k_proj16(float* __restrict__ out)
{
    gemm128_body<true>(g_ao, g_wproj16, out, D_, D_);
}

// ===========================================================================
// k_zsum: Z[k] = sum_q exp(scale * K[k]·Q[q])   per (b,h)   [R4 verbatim]
// ===========================================================================
__global__ void k_zsum()
{
    __shared__ __align__(16) __half sK[128 * LS];
    __shared__ __align__(16) __half sQ[64 * LS];

    const int kc = blockIdx.x, bh = blockIdx.y;
    const int b = bh >> 4, h = bh & 15;
    const int t = threadIdx.x;
    const int warp = t >> 5, lane = t & 31;

    {
        const __half* Kg = g_qkv + ((long)b * T_ + kc * 128) * D3 + D_ + h * DH_;
        const int r_ = t >> 3, c_ = (t & 7) * 8;
#pragma unroll
        for (int p = 0; p < 4; ++p) {
            int r = r_ + p * 32;
            *(uint4*)&sK[r * LS + c_] = *(const uint4*)(Kg + (long)r * D3 + c_);
        }
    }
    __syncthreads();

    u32 a[4][4];
    {
        const u32 abase = smem_u32(&sK[(warp * 16 + (lane & 15)) * LS + (lane >> 4) * 8]);
#pragma unroll
        for (int ks = 0; ks < 4; ++ks)
            ldsm_x4(a[ks][0], a[ks][1], a[ks][2], a[ks][3], abase + (u32)(ks * 16 * 2));
    }

    float zacc0 = 0.0f, zacc1 = 0.0f;
    const __half* Qg = g_qkv + (long)b * T_ * D3 + h * DH_;
    const u32 bqbase = smem_u32(&sQ[(lane & 7) * LS + ((lane >> 3) & 1) * 8]);
    const int r2 = t >> 2, c2 = (t & 3) * 8;

    for (int qt = 0; qt < 16; ++qt) {
        __syncthreads();
        const __half* Qsrc = Qg + (long)(qt * 64 + r2) * D3;
        *(uint4*)&sQ[r2 * LS + c2]      = *(const uint4*)(Qsrc + c2);
        *(uint4*)&sQ[r2 * LS + c2 + 32] = *(const uint4*)(Qsrc + c2 + 32);
        __syncthreads();

        float c[8][4];
#pragma unroll
        for (int ni = 0; ni < 8; ++ni)
#pragma unroll
            for (int j = 0; j < 4; ++j) c[ni][j] = 0.0f;

#pragma unroll
        for (int ks = 0; ks < 4; ++ks) {
            u32 bq[8][2];
#pragma unroll
            for (int ni = 0; ni < 8; ++ni)
                ldsm_x2(bq[ni][0], bq[ni][1],
                        bqbase + (u32)((ni * 8 * LS + ks * 16) * 2));
#pragma unroll
            for (int ni = 0; ni < 8; ++ni)
                mma16816(c[ni], a[ks][0], a[ks][1], a[ks][2], a[ks][3],
                         bq[ni][0], bq[ni][1]);
        }

#pragma unroll
        for (int ni = 0; ni < 8; ++ni) {
            zacc0 += __expf(0.125f * c[ni][0]) + __expf(0.125f * c[ni][1]);
            zacc1 += __expf(0.125f * c[ni][2]) + __expf(0.125f * c[ni][3]);
        }
    }

    zacc0 += __shfl_xor_sync(0xffffffffu, zacc0, 1);
    zacc0 += __shfl_xor_sync(0xffffffffu, zacc0, 2);
    zacc1 += __shfl_xor_sync(0xffffffffu, zacc1, 1);
    zacc1 += __shfl_xor_sync(0xffffffffu, zacc1, 2);
    if ((lane & 3) == 0) {
        int krow = kc * 128 + warp * 16 + (lane >> 2);
        g_Z[(long)bh * T_ + krow]     = zacc0;
        g_Z[(long)bh * T_ + krow + 8] = zacc1;
    }
}

// ===========================================================================
// k_attn: out[q,d] = sum_k exp(scale*q·k)/Z[k] * V[k,d]     [R4 verbatim]
// ===========================================================================
__global__ void k_attn()
{
    __shared__ __align__(16) __half sP[128 * LS];
    __shared__ __align__(16) __half sK[64 * LS];
    __shared__ __align__(16) __half sV[64 * LS];
    __shared__ float sRZ[64];

    const int qt = blockIdx.x, bh = blockIdx.y;
    const int b = bh >> 4, h = bh & 15;
    const int t = threadIdx.x;
    const int warp = t >> 5, lane = t & 31;
    const int g = lane >> 2, tq = lane & 3;

    {
        const __half* Qg = g_qkv + ((long)b * T_ + qt * 128) * D3 + h * DH_;
        const int r_ = t >> 3, c_ = (t & 7) * 8;
#pragma unroll
        for (int p = 0; p < 4; ++p) {
            int r = r_ + p * 32;
            *(uint4*)&sP[r * LS + c_] = *(const uint4*)(Qg + (long)r * D3 + c_);
        }
    }
    __syncthreads();

    u32 aq[4][4];
    const u32 pbase = smem_u32(&sP[(warp * 16 + (lane & 15)) * LS + (lane >> 4) * 8]);
#pragma unroll
    for (int ks = 0; ks < 4; ++ks)
        ldsm_x4(aq[ks][0], aq[ks][1], aq[ks][2], aq[ks][3], pbase + (u32)(ks * 16 * 2));

    float o[8][4];
#pragma unroll
    for (int ni = 0; ni < 8; ++ni)
#pragma unroll
        for (int j = 0; j < 4; ++j) o[ni][j] = 0.0f;

    const __half* Kg = g_qkv + (long)b * T_ * D3 + D_ + h * DH_;
    const __half* Vg = g_qkv + (long)b * T_ * D3 + 2 * D_ + h * DH_;
    const float* Zp = g_Z + (long)bh * T_;
    const u32 bkbase = smem_u32(&sK[(lane & 7) * LS + ((lane >> 3) & 1) * 8]);
    const u32 bvbase = smem_u32(&sV[(lane & 15) * LS]);
    const int r2 = t >> 2, c2 = (t & 3) * 8;

    for (int kc = 0; kc < 16; ++kc) {
        __syncthreads();
        {
            const __half* Ksrc = Kg + (long)(kc * 64 + r2) * D3;
            const __half* Vsrc = Vg + (long)(kc * 64 + r2) * D3;
            *(uint4*)&sK[r2 * LS + c2]      = *(const uint4*)(Ksrc + c2);
            *(uint4*)&sK[r2 * LS + c2 + 32] = *(const uint4*)(Ksrc + c2 + 32);
            *(uint4*)&sV[r2 * LS + c2]      = *(const uint4*)(Vsrc + c2);
            *(uint4*)&sV[r2 * LS + c2 + 32] = *(const uint4*)(Vsrc + c2 + 32);
            if (t < 64) sRZ[t] = 1.0f / Zp[kc * 64 + t];
        }
        __syncthreads();

        float c[8][4];
#pragma unroll
        for (int ni = 0; ni < 8; ++ni)
#pragma unroll
            for (int j = 0; j < 4; ++j) c[ni][j] = 0.0f;

#pragma unroll
        for (int ks = 0; ks < 4; ++ks) {
            u32 bk[8][2];
#pragma unroll
            for (int ni = 0; ni < 8; ++ni)
                ldsm_x2(bk[ni][0], bk[ni][1],
                        bkbase + (u32)((ni * 8 * LS + ks * 16) * 2));
#pragma unroll
            for (int ni = 0; ni < 8; ++ni)
                mma16816(c[ni], aq[ks][0], aq[ks][1], aq[ks][2], aq[ks][3],
                         bk[ni][0], bk[ni][1]);
        }

#pragma unroll
        for (int ni = 0; ni < 8; ++ni) {
            int col = ni * 8 + tq * 2;
            float rz0 = sRZ[col], rz1 = sRZ[col + 1];
            __half2 p01 = __floats2half2_rn(__expf(0.125f * c[ni][0]) * rz0,
                                            __expf(0.125f * c[ni][1]) * rz1);
            __half2 p23 = __floats2half2_rn(__expf(0.125f * c[ni][2]) * rz0,
                                            __expf(0.125f * c[ni][3]) * rz1);
            *(__half2*)&sP[(warp * 16 + g) * LS + col]     = p01;
            *(__half2*)&sP[(warp * 16 + g + 8) * LS + col] = p23;
        }
        __syncthreads();

#pragma unroll
        for (int ks = 0; ks < 4; ++ks) {
            u32 ap[4];
            ldsm_x4(ap[0], ap[1], ap[2], ap[3], pbase + (u32)(ks * 16 * 2));
            u32 bv[8][2];
#pragma unroll
            for (int nd = 0; nd < 8; ++nd)
                ldsm_x2t(bv[nd][0], bv[nd][1],
                         bvbase + (u32)((ks * 16 * LS + nd * 8) * 2));
#pragma unroll
            for (int nd = 0; nd < 8; ++nd)
                mma16816(o[nd], ap[0], ap[1], ap[2], ap[3], bv[nd][0], bv[nd][1]);
        }
    }

    __half* Og = g_ao + ((long)b * T_ + qt * 128) * D_ + h * DH_;
#pragma unroll
    for (int nd = 0; nd < 8; ++nd) {
        int row = warp * 16 + g;
        int col = nd * 8 + tq * 2;
        *(__half2*)(Og + (long)row * D_ + col)       = __floats2half2_rn(o[nd][0], o[nd][1]);
        *(__half2*)(Og + (long)(row + 8) * D_ + col) = __floats2half2_rn(o[nd][2], o[nd][3]);
    }
}

// ---------------------------------------------------------------------------
extern "C" void kernel_launch(void* const* d_in, const int* in_sizes, int n_in,
                              void* d_out, int out_size)
{
    const float* x      = (const float*)d_in[0];   // [8,1024,1024]
    const float* w_qkv  = (const float*)d_in[1];   // [3072,1024]
    const float* w_proj = (const float*)d_in[2];   // [1024,1024]
    float* out = (float*)d_out;                    // [8,1024,1024]

    k_f2h_x    <<<(long)BT * D_ / 2048, 256>>>(x);
    k_f2h_wqkv <<<(long)D3 * D_ / 2048, 256>>>(w_qkv);
    k_f2h_wproj<<<(long)D_ * D_ / 2048, 256>>>(w_proj);

    k_qkv16 <<<dim3(D3 / 128, BT / 128), 256>>>();
    k_zsum  <<<dim3(T_ / 128, B_ * H_), 256>>>();
    k_attn  <<<dim3(T_ / 128, B_ * H_), 256>>>();
    k_proj16<<<dim3(D_ / 128, BT / 128), 256>>>(out);
}

// round 10
// speedup vs baseline: 6.3080x; 1.0264x over previous
#include <cuda_runtime.h>
#include <cuda_fp16.h>

// Problem constants
#define B_  8
#define T_  1024
#define D_  1024
#define H_  16
#define DH_ 64
#define BT  (B_*T_)        // 8192
#define D3  (3*D_)         // 3072

#define KSD 40             // dense gemm smem row stride (32 + 8 pad), halves
#define LS 72              // attention smem row stride (64 + 8 pad), halves

typedef unsigned int u32;

// Scratch (__device__ globals — referenced ONLY from device code!)
static __device__ __half g_x16[(long)BT * D_];       // x fp16, 16MB
static __device__ __half g_wqkv16[(long)D3 * D_];    // W_qkv fp16, 6MB
static __device__ __half g_wproj16[(long)D_ * D_];   // W_proj fp16, 2MB
static __device__ __half g_qkv[(long)BT * D3];       // [t][3D] fp16, 48MB
static __device__ float  g_Z[(long)B_*H_*T_];        // softmax denominators
static __device__ __half g_ao[(long)BT * D_];        // [t][D] fp16, 16MB

// ---------------------------------------------------------------------------
// PTX helpers
// ---------------------------------------------------------------------------
__device__ __forceinline__ u32 smem_u32(const void* p) {
    return (u32)__cvta_generic_to_shared(p);
}
__device__ __forceinline__ void ldsm_x4(u32& r0, u32& r1, u32& r2, u32& r3, u32 a) {
    asm volatile("ldmatrix.sync.aligned.m8n8.x4.shared.b16 {%0,%1,%2,%3},[%4];"
                 : "=r"(r0), "=r"(r1), "=r"(r2), "=r"(r3) : "r"(a));
}
__device__ __forceinline__ void ldsm_x2(u32& r0, u32& r1, u32 a) {
    asm volatile("ldmatrix.sync.aligned.m8n8.x2.shared.b16 {%0,%1},[%2];"
                 : "=r"(r0), "=r"(r1) : "r"(a));
}
__device__ __forceinline__ void ldsm_x2t(u32& r0, u32& r1, u32 a) {
    asm volatile("ldmatrix.sync.aligned.m8n8.x2.trans.shared.b16 {%0,%1},[%2];"
                 : "=r"(r0), "=r"(r1) : "r"(a));
}
__device__ __forceinline__ void mma16816(float c[4],
                                         u32 a0, u32 a1, u32 a2, u32 a3,
                                         u32 b0, u32 b1) {
    asm volatile("mma.sync.aligned.m16n8k16.row.col.f32.f16.f16.f32 "
                 "{%0,%1,%2,%3},{%4,%5,%6,%7},{%8,%9},{%0,%1,%2,%3};"
                 : "+f"(c[0]), "+f"(c[1]), "+f"(c[2]), "+f"(c[3])
                 : "r"(a0), "r"(a1), "r"(a2), "r"(a3), "r"(b0), "r"(b1));
}
__device__ __forceinline__ void cpa16(u32 dst, const void* src) {
    asm volatile("cp.async.cg.shared.global [%0],[%1],16;" :: "r"(dst), "l"(src));
}
#define CP_COMMIT() asm volatile("cp.async.commit_group;")
#define CP_WAIT0()  asm volatile("cp.async.wait_group 0;")

// ---------------------------------------------------------------------------
// fp32 -> fp16 conversion (globals named in device code only)
// ---------------------------------------------------------------------------
__device__ __forceinline__ void f2h_body(const float* __restrict__ s, __half* __restrict__ d)
{
    long i = ((long)blockIdx.x * blockDim.x + threadIdx.x) * 8;
    float4 v0 = *(const float4*)(s + i);
    float4 v1 = *(const float4*)(s + i + 4);
    uint4 o;
    __half2* hp = (__half2*)&o;
    hp[0] = __floats2half2_rn(v0.x, v0.y);
    hp[1] = __floats2half2_rn(v0.z, v0.w);
    hp[2] = __floats2half2_rn(v1.x, v1.y);
    hp[3] = __floats2half2_rn(v1.z, v1.w);
    *(uint4*)(d + i) = o;
}
__global__ void k_f2h_x(const float* __restrict__ s)     { f2h_body(s, g_x16); }
__global__ void k_f2h_wqkv(const float* __restrict__ s)  { f2h_body(s, g_wqkv16); }
__global__ void k_f2h_wproj(const float* __restrict__ s) { f2h_body(s, g_wproj16); }

// ---------------------------------------------------------------------------
// Dense NT GEMM body (R8-proven): 128x128x32, cp.async 2-stage.
// ---------------------------------------------------------------------------
template<bool CF32>
__device__ __forceinline__ void gemm128_body(
    const __half* __restrict__ A, const __half* __restrict__ B, void* Cp,
    int K, long ldc)
{
    __shared__ __align__(16) __half sA[2][128 * KSD];
    __shared__ __align__(16) __half sB[2][128 * KSD];

    const int t = threadIdx.x;
    const int warp = t >> 5, lane = t & 31;
    const int wm = warp >> 2, wn = warp & 3;
    const long m0 = (long)blockIdx.y * 128, n0 = (long)blockIdx.x * 128;

    const int lr = t >> 2;
    const int lc = (t & 3) * 8;

    const __half* Ag0 = A + (m0 + lr) * (long)K + lc;
    const __half* Ag1 = Ag0 + 64 * (long)K;
    const __half* Bg0 = B + (n0 + lr) * (long)K + lc;
    const __half* Bg1 = Bg0 + 64 * (long)K;

    const u32 dA0 = smem_u32(&sA[0][lr * KSD + lc]);
    const u32 dA1 = smem_u32(&sA[0][(lr + 64) * KSD + lc]);
    const u32 dB0 = smem_u32(&sB[0][lr * KSD + lc]);
    const u32 dB1 = smem_u32(&sB[0][(lr + 64) * KSD + lc]);
    const u32 SBY = (u32)sizeof(sA[0]);

    cpa16(dA0, Ag0); cpa16(dA1, Ag1);
    cpa16(dB0, Bg0); cpa16(dB1, Bg1);
    CP_COMMIT();

    float acc[4][4][4];
#pragma unroll
    for (int i = 0; i < 4; ++i)
#pragma unroll
        for (int j = 0; j < 4; ++j)
#pragma unroll
            for (int k = 0; k < 4; ++k) acc[i][j][k] = 0.0f;

    const u32 abase = smem_u32(&sA[0][(wm * 64 + (lane & 15)) * KSD + (lane >> 4) * 8]);
    const u32 bbase = smem_u32(&sB[0][(wn * 32 + (lane & 7)) * KSD + ((lane >> 3) & 1) * 8]);

    const int KT = K >> 5;
    for (int kt = 0; kt < KT; ++kt) {
        CP_WAIT0();
        __syncthreads();
        const int st = kt & 1;

        if (kt + 1 < KT) {
            const long ko = (long)(kt + 1) * 32;
            const u32 o = (u32)(st ^ 1) * SBY;
            cpa16(dA0 + o, Ag0 + ko); cpa16(dA1 + o, Ag1 + ko);
            cpa16(dB0 + o, Bg0 + ko); cpa16(dB1 + o, Bg1 + ko);
        }
        CP_COMMIT();

        const u32 ab = abase + (u32)st * SBY;
        const u32 bb = bbase + (u32)st * SBY;
#pragma unroll
        for (int ks = 0; ks < 2; ++ks) {
            u32 a[4][4], b[4][2];
#pragma unroll
            for (int mi = 0; mi < 4; ++mi)
                ldsm_x4(a[mi][0], a[mi][1], a[mi][2], a[mi][3],
                        ab + (u32)((mi * 16 * KSD + ks * 16) * 2));
#pragma unroll
            for (int ni = 0; ni < 4; ++ni)
                ldsm_x2(b[ni][0], b[ni][1],
                        bb + (u32)((ni * 8 * KSD + ks * 16) * 2));
#pragma unroll
            for (int mi = 0; mi < 4; ++mi)
#pragma unroll
                for (int ni = 0; ni < 4; ++ni)
                    mma16816(acc[mi][ni], a[mi][0], a[mi][1], a[mi][2], a[mi][3],
                             b[ni][0], b[ni][1]);
        }
    }

    const int g = lane >> 2, tq = lane & 3;
#pragma unroll
    for (int mi = 0; mi < 4; ++mi) {
#pragma unroll
        for (int ni = 0; ni < 4; ++ni) {
            long row = m0 + wm * 64 + mi * 16 + g;
            long col = n0 + wn * 32 + ni * 8 + tq * 2;
            if (CF32) {
                float* C = (float*)Cp;
                *(float2*)(C + row * ldc + col)       = make_float2(acc[mi][ni][0], acc[mi][ni][1]);
                *(float2*)(C + (row + 8) * ldc + col) = make_float2(acc[mi][ni][2], acc[mi][ni][3]);
            } else {
                __half* C = (__half*)Cp;
                *(__half2*)(C + row * ldc + col)       = __floats2half2_rn(acc[mi][ni][0], acc[mi][ni][1]);
                *(__half2*)(C + (row + 8) * ldc + col) = __floats2half2_rn(acc[mi][ni][2], acc[mi][ni][3]);
            }
        }
    }
}

__global__ void __launch_bounds__(256, 2) k_qkv16()
{
    gemm128_body<false>(g_x16, g_wqkv16, g_qkv, D_, D3);
}
__global__ void __launch_bounds__(256, 2) k_proj16(float* __restrict__ out)
{
    gemm128_body<true>(g_ao, g_wproj16, out, D_, D_);
}

// ===========================================================================
// k_zsum: Z[k] = sum_q exp(scale * K[k]·Q[q])  — cp.async double-buffered Q
// ===========================================================================
__global__ void k_zsum()
{
    __shared__ __align__(16) __half sK[128 * LS];
    __shared__ __align__(16) __half sQ[2][64 * LS];

    const int kc = blockIdx.x, bh = blockIdx.y;
    const int b = bh >> 4, h = bh & 15;
    const int t = threadIdx.x;
    const int warp = t >> 5, lane = t & 31;
    const int r2 = t >> 2, c2 = (t & 3) * 8;

    const __half* Qg = g_qkv + (long)b * T_ * D3 + h * DH_;
    const u32 dQ = smem_u32(&sQ[0][r2 * LS + c2]);
    const u32 QSBY = (u32)sizeof(sQ[0]);

    // Prologue: issue Q tile 0 (overlaps with K load below)
    {
        const __half* Qsrc = Qg + (long)r2 * D3;
        cpa16(dQ, Qsrc + c2);
        cpa16(dQ + 64, Qsrc + c2 + 32);
        CP_COMMIT();
    }

    // Load K chunk [128][64]
    {
        const __half* Kg = g_qkv + ((long)b * T_ + kc * 128) * D3 + D_ + h * DH_;
        const int r_ = t >> 3, c_ = (t & 7) * 8;
#pragma unroll
        for (int p = 0; p < 4; ++p) {
            int r = r_ + p * 32;
            *(uint4*)&sK[r * LS + c_] = *(const uint4*)(Kg + (long)r * D3 + c_);
        }
    }
    __syncthreads();

    u32 a[4][4];
    {
        const u32 abase = smem_u32(&sK[(warp * 16 + (lane & 15)) * LS + (lane >> 4) * 8]);
#pragma unroll
        for (int ks = 0; ks < 4; ++ks)
            ldsm_x4(a[ks][0], a[ks][1], a[ks][2], a[ks][3], abase + (u32)(ks * 16 * 2));
    }

    float zacc0 = 0.0f, zacc1 = 0.0f;
    const u32 bqbase = smem_u32(&sQ[0][(lane & 7) * LS + ((lane >> 3) & 1) * 8]);

    for (int qt = 0; qt < 16; ++qt) {
        const int st = qt & 1;
        CP_WAIT0();
        __syncthreads();

        if (qt + 1 < 16) {
            const __half* Qsrc = Qg + (long)((qt + 1) * 64 + r2) * D3;
            const u32 o = (u32)(st ^ 1) * QSBY;
            cpa16(dQ + o, Qsrc + c2);
            cpa16(dQ + o + 64, Qsrc + c2 + 32);
        }
        CP_COMMIT();

        float c[8][4];
#pragma unroll
        for (int ni = 0; ni < 8; ++ni)
#pragma unroll
            for (int j = 0; j < 4; ++j) c[ni][j] = 0.0f;

        const u32 bq0 = bqbase + (u32)st * QSBY;
#pragma unroll
        for (int ks = 0; ks < 4; ++ks) {
            u32 bq[8][2];
#pragma unroll
            for (int ni = 0; ni < 8; ++ni)
                ldsm_x2(bq[ni][0], bq[ni][1],
                        bq0 + (u32)((ni * 8 * LS + ks * 16) * 2));
#pragma unroll
            for (int ni = 0; ni < 8; ++ni)
                mma16816(c[ni], a[ks][0], a[ks][1], a[ks][2], a[ks][3],
                         bq[ni][0], bq[ni][1]);
        }

#pragma unroll
        for (int ni = 0; ni < 8; ++ni) {
            zacc0 += __expf(0.125f * c[ni][0]) + __expf(0.125f * c[ni][1]);
            zacc1 += __expf(0.125f * c[ni][2]) + __expf(0.125f * c[ni][3]);
        }
    }

    zacc0 += __shfl_xor_sync(0xffffffffu, zacc0, 1);
    zacc0 += __shfl_xor_sync(0xffffffffu, zacc0, 2);
    zacc1 += __shfl_xor_sync(0xffffffffu, zacc1, 1);
    zacc1 += __shfl_xor_sync(0xffffffffu, zacc1, 2);
    if ((lane & 3) == 0) {
        int krow = kc * 128 + warp * 16 + (lane >> 2);
        g_Z[(long)bh * T_ + krow]     = zacc0;
        g_Z[(long)bh * T_ + krow + 8] = zacc1;
    }
}

// ===========================================================================
// k_attn: out[q,d] = sum_k exp(scale*q·k)/Z[k] * V[k,d]
//         cp.async double-buffered K/V chunks
// ===========================================================================
__global__ void k_attn()
{
    __shared__ __align__(16) __half sP[128 * LS];
    __shared__ __align__(16) __half sK[2][64 * LS];
    __shared__ __align__(16) __half sV[2][64 * LS];
    __shared__ float sRZ[2][64];

    const int qt = blockIdx.x, bh = blockIdx.y;
    const int b = bh >> 4, h = bh & 15;
    const int t = threadIdx.x;
    const int warp = t >> 5, lane = t & 31;
    const int g = lane >> 2, tq = lane & 3;
    const int r2 = t >> 2, c2 = (t & 3) * 8;

    const __half* Kg = g_qkv + (long)b * T_ * D3 + D_ + h * DH_;
    const __half* Vg = g_qkv + (long)b * T_ * D3 + 2 * D_ + h * DH_;
    const float* Zp = g_Z + (long)bh * T_;

    const u32 dK = smem_u32(&sK[0][r2 * LS + c2]);
    const u32 dV = smem_u32(&sV[0][r2 * LS + c2]);
    const u32 CSBY = (u32)sizeof(sK[0]);

    // Prologue: issue K/V chunk 0 (overlaps with Q load below)
    {
        const __half* Ksrc = Kg + (long)r2 * D3;
        const __half* Vsrc = Vg + (long)r2 * D3;
        cpa16(dK, Ksrc + c2);      cpa16(dK + 64, Ksrc + c2 + 32);
        cpa16(dV, Vsrc + c2);      cpa16(dV + 64, Vsrc + c2 + 32);
        CP_COMMIT();
    }

    // Load Q tile [128][64] into sP staging
    {
        const __half* Qg = g_qkv + ((long)b * T_ + qt * 128) * D3 + h * DH_;
        const int r_ = t >> 3, c_ = (t & 7) * 8;
#pragma unroll
        for (int p = 0; p < 4; ++p) {
            int r = r_ + p * 32;
            *(uint4*)&sP[r * LS + c_] = *(const uint4*)(Qg + (long)r * D3 + c_);
        }
    }
    __syncthreads();

    u32 aq[4][4];
    const u32 pbase = smem_u32(&sP[(warp * 16 + (lane & 15)) * LS + (lane >> 4) * 8]);
#pragma unroll
    for (int ks = 0; ks < 4; ++ks)
        ldsm_x4(aq[ks][0], aq[ks][1], aq[ks][2], aq[ks][3], pbase + (u32)(ks * 16 * 2));

    float o[8][4];
#pragma unroll
    for (int ni = 0; ni < 8; ++ni)
#pragma unroll
        for (int j = 0; j < 4; ++j) o[ni][j] = 0.0f;

    const u32 bkbase = smem_u32(&sK[0][(lane & 7) * LS + ((lane >> 3) & 1) * 8]);
    const u32 bvbase = smem_u32(&sV[0][(lane & 15) * LS]);

    for (int kc = 0; kc < 16; ++kc) {
        const int st = kc & 1;
        CP_WAIT0();
        if (t < 64) sRZ[st][t] = 1.0f / Zp[kc * 64 + t];
        __syncthreads();

        // Issue next K/V chunk (overlaps with both MMA phases below)
        if (kc + 1 < 16) {
            const __half* Ksrc = Kg + (long)((kc + 1) * 64 + r2) * D3;
            const __half* Vsrc = Vg + (long)((kc + 1) * 64 + r2) * D3;
            const u32 oo = (u32)(st ^ 1) * CSBY;
            cpa16(dK + oo, Ksrc + c2);      cpa16(dK + oo + 64, Ksrc + c2 + 32);
            cpa16(dV + oo, Vsrc + c2);      cpa16(dV + oo + 64, Vsrc + c2 + 32);
        }
        CP_COMMIT();

        // S tile = Q·K^T
        float c[8][4];
#pragma unroll
        for (int ni = 0; ni < 8; ++ni)
#pragma unroll
            for (int j = 0; j < 4; ++j) c[ni][j] = 0.0f;

        const u32 bk0 = bkbase + (u32)st * CSBY;
#pragma unroll
        for (int ks = 0; ks < 4; ++ks) {
            u32 bk[8][2];
#pragma unroll
            for (int ni = 0; ni < 8; ++ni)
                ldsm_x2(bk[ni][0], bk[ni][1],
                        bk0 + (u32)((ni * 8 * LS + ks * 16) * 2));
#pragma unroll
            for (int ni = 0; ni < 8; ++ni)
                mma16816(c[ni], aq[ks][0], aq[ks][1], aq[ks][2], aq[ks][3],
                         bk[ni][0], bk[ni][1]);
        }

        // p = exp(scale*s)/Z[k] -> fp16 P in smem
#pragma unroll
        for (int ni = 0; ni < 8; ++ni) {
            int col = ni * 8 + tq * 2;
            float rz0 = sRZ[st][col], rz1 = sRZ[st][col + 1];
            __half2 p01 = __floats2half2_rn(__expf(0.125f * c[ni][0]) * rz0,
                                            __expf(0.125f * c[ni][1]) * rz1);
            __half2 p23 = __floats2half2_rn(__expf(0.125f * c[ni][2]) * rz0,
                                            __expf(0.125f * c[ni][3]) * rz1);
            *(__half2*)&sP[(warp * 16 + g) * LS + col]     = p01;
            *(__half2*)&sP[(warp * 16 + g + 8) * LS + col] = p23;
        }
        __syncthreads();

        // O += P·V
        const u32 bv0 = bvbase + (u32)st * CSBY;
#pragma unroll
        for (int ks = 0; ks < 4; ++ks) {
            u32 ap[4];
            ldsm_x4(ap[0], ap[1], ap[2], ap[3], pbase + (u32)(ks * 16 * 2));
            u32 bv[8][2];
#pragma unroll
            for (int nd = 0; nd < 8; ++nd)
                ldsm_x2t(bv[nd][0], bv[nd][1],
                         bv0 + (u32)((ks * 16 * LS + nd * 8) * 2));
#pragma unroll
            for (int nd = 0; nd < 8; ++nd)
                mma16816(o[nd], ap[0], ap[1], ap[2], ap[3], bv[nd][0], bv[nd][1]);
        }
        __syncthreads();   // P-buffer reuse guard before next iteration's P write
    }

    __half* Og = g_ao + ((long)b * T_ + qt * 128) * D_ + h * DH_;
#pragma unroll
    for (int nd = 0; nd < 8; ++nd) {
        int row = warp * 16 + g;
        int col = nd * 8 + tq * 2;
        *(__half2*)(Og + (long)row * D_ + col)       = __floats2half2_rn(o[nd][0], o[nd][1]);
        *(__half2*)(Og + (long)(row + 8) * D_ + col) = __floats2half2_rn(o[nd][2], o[nd][3]);
    }
}

// ---------------------------------------------------------------------------
extern "C" void kernel_launch(void* const* d_in, const int* in_sizes, int n_in,
                              void* d_out, int out_size)
{
    const float* x      = (const float*)d_in[0];   // [8,1024,1024]
    const float* w_qkv  = (const float*)d_in[1];   // [3072,1024]
    const float* w_proj = (const float*)d_in[2];   // [1024,1024]
    float* out = (float*)d_out;                    // [8,1024,1024]

    k_f2h_x    <<<(long)BT * D_ / 2048, 256>>>(x);
    k_f2h_wqkv <<<(long)D3 * D_ / 2048, 256>>>(w_qkv);
    k_f2h_wproj<<<(long)D_ * D_ / 2048, 256>>>(w_proj);

    k_qkv16 <<<dim3(D3 / 128, BT / 128), 256>>>();
    k_zsum  <<<dim3(T_ / 128, B_ * H_), 256>>>();
    k_attn  <<<dim3(T_ / 128, B_ * H_), 256>>>();
    k_proj16<<<dim3(D_ / 128, BT / 128), 256>>>(out);
}